// round 8
// baseline (speedup 1.0000x reference)
#include <cuda_runtime.h>
#include <cuda_bf16.h>
#include <cstdint>

// ---------------------------------------------------------------------------
// FNO spectral block: B=2, H=1024, W=1024, C=32, modes rows {0..31,992..1023},
// cols 0..31.  Factored into 4 partial-DFT GEMM stages, fp32 with f32x2 FMA.
// ---------------------------------------------------------------------------

#define Bn 2
#define Hn 1024
#define Wn 1024
#define Cn 32

// ---- device scratch (allocation-free) ----
__device__ float g_FAT[64 * 1024];                  // [fcol][w]: fcol=2k2 -> cos, 2k2+1 -> -sin
__device__ float g_GD [1024 * 64];                  // [w][fcol]: sc*cos, -sc*sin
__device__ float g_EB4[1024 * 64 * 4];              // [h][k1i]: (c,-s, s,c)   e^{-i th}
__device__ float g_EC4[1024 * 64 * 4];              // [h][k1i]: (c, s,-s,c)/H e^{+i th}/H
__device__ float g_Wc [32 * 64 * 32 * 2];           // combined w0*(w1|w2), complex
__device__ float g_A  [(size_t)Bn * Cn * Hn * 64];  // [b][c][h][fcol]
__device__ float g_Xp [8 * 32 * 64 * 32 * 2];       // [hq*2+b][c][k1i][k2] complex partials
__device__ float g_XW [(size_t)Bn * Cn * 64 * 64];  // [b][c][k1i][2k2]
__device__ float g_Z  [(size_t)Bn * Hn * Cn * 64];  // [b][h][c][fcol]

// ---- packed fp32x2 helpers (Blackwell f32x2 pipe) ----
__device__ __forceinline__ void fma2(unsigned long long& acc,
                                     unsigned long long a,
                                     unsigned long long b) {
    asm("fma.rn.f32x2 %0, %1, %2, %0;" : "+l"(acc) : "l"(a), "l"(b));
}
__device__ __forceinline__ unsigned long long pack2(float x, float y) {
    unsigned long long r;
    asm("mov.b64 %0, {%1, %2};" : "=l"(r) : "f"(x), "f"(y));
    return r;
}
__device__ __forceinline__ float2 unpack2(unsigned long long v) {
    float2 r;
    asm("mov.b64 {%0, %1}, %2;" : "=f"(r.x), "=f"(r.y) : "l"(v));
    return r;
}

// ---------------------------------------------------------------------------
// Twiddle tables.  Exact integer mod-1024 phase + double sincospi.
// ---------------------------------------------------------------------------
__global__ void k_init_tables() {
    const int row = blockIdx.x;     // w for FAT/GD, h for EB4/EC4
    const int t = threadIdx.x;      // 64
    if (t < 32) {
        const int k2 = t;
        const int r = (k2 * row) & 1023;
        double s, c;
        sincospi((double)r / 512.0, &s, &c);
        g_FAT[(2 * k2)     * 1024 + row] = (float)c;
        g_FAT[(2 * k2 + 1) * 1024 + row] = (float)(-s);
        const double sc = (k2 == 0 ? 1.0 : 2.0) / 1024.0;
        g_GD[row * 64 + 2 * k2]     = (float)(sc * c);
        g_GD[row * 64 + 2 * k2 + 1] = (float)(-sc * s);
    }
    {
        const int k1i = t;
        const int k1 = (k1i < 32) ? k1i : (960 + k1i);  // 992..1023
        const int r = (k1 * row) & 1023;
        double s, c;
        sincospi((double)r / 512.0, &s, &c);
        float* eb = &g_EB4[(row * 64 + k1i) * 4];
        eb[0] = (float)c;  eb[1] = (float)(-s);
        eb[2] = (float)s;  eb[3] = (float)c;
        const double inv = 1.0 / 1024.0;
        float* ec = &g_EC4[(row * 64 + k1i) * 4];
        ec[0] = (float)(c * inv);  ec[1] = (float)(s * inv);
        ec[2] = (float)(-s * inv); ec[3] = (float)(c * inv);
    }
}

// Combined weights Wc[c][k1i][k2] = w0[c] * (w1|w2)[c, m1, k2], complex.
__global__ void k_init_w(const float* __restrict__ w0r, const float* __restrict__ w0i,
                         const float* __restrict__ w1r, const float* __restrict__ w1i,
                         const float* __restrict__ w2r, const float* __restrict__ w2i) {
    const int idx = blockIdx.x * 256 + threadIdx.x;   // 65536
    const int k2 = idx & 31;
    const int k1i = (idx >> 5) & 63;
    const int c = idx >> 11;
    const float ar = w0r[c], ai = w0i[c];
    float br, bi;
    if (k1i < 32) {
        const int o = (c * 32 + k1i) * 32 + k2;
        br = w1r[o]; bi = w1i[o];
    } else {
        const int o = (c * 32 + (k1i - 32)) * 32 + k2;
        br = w2r[o]; bi = w2i[o];
    }
    g_Wc[idx * 2]     = ar * br - ai * bi;
    g_Wc[idx * 2 + 1] = ar * bi + ai * br;
}

// ---------------------------------------------------------------------------
// Stage A: A[b,c,h,fcol] = sum_w x[b,h,w,c] * FAT[fcol,w].
// CTA per (h,b).  M=32(c) x N=64(fcol) x K=1024(w), K-chunks of 64.
// Thread: 4 c x 2 fcol, f32x2 packs even/odd-w partial sums.
// ---------------------------------------------------------------------------
__global__ void __launch_bounds__(256) kA(const float* __restrict__ x) {
    const int h = blockIdx.x, b = blockIdx.y;
    __shared__ __align__(16) float xs[32 * 66];    // [c][w]
    __shared__ __align__(16) float FAs[64 * 66];   // [fcol][w]
    const int t = threadIdx.x;
    const int cg = (t & 7) * 4;
    const int fg = (t >> 3) * 2;
    unsigned long long acc[4][2] = {};
    const float* xrow = x + ((size_t)(b * 1024 + h)) * 1024 * 32;

    for (int w0 = 0; w0 < 1024; w0 += 64) {
        // xs: transpose-load 64w x 32c
#pragma unroll
        for (int k = 0; k < 2; k++) {
            const int idx = t + k * 256;             // 512 float4
            const int ww = idx >> 3, c4 = (idx & 7) * 4;
            const float4 v = *(const float4*)&xrow[(w0 + ww) * 32 + c4];
            xs[(c4 + 0) * 66 + ww] = v.x;
            xs[(c4 + 1) * 66 + ww] = v.y;
            xs[(c4 + 2) * 66 + ww] = v.z;
            xs[(c4 + 3) * 66 + ww] = v.w;
        }
        // FAs: 64 rows x 32 float2
#pragma unroll
        for (int k = 0; k < 8; k++) {
            const int idx = t + k * 256;             // 2048 float2
            const int fr = idx >> 5, wp2 = (idx & 31) * 2;
            *(float2*)&FAs[fr * 66 + wp2] = *(const float2*)&g_FAT[fr * 1024 + w0 + wp2];
        }
        __syncthreads();
#pragma unroll 8
        for (int wp = 0; wp < 32; wp++) {
            const unsigned long long fv0 = *(const unsigned long long*)&FAs[fg * 66 + 2 * wp];
            const unsigned long long fv1 = *(const unsigned long long*)&FAs[(fg + 1) * 66 + 2 * wp];
#pragma unroll
            for (int i = 0; i < 4; i++) {
                const unsigned long long xv = *(const unsigned long long*)&xs[(cg + i) * 66 + 2 * wp];
                fma2(acc[i][0], xv, fv0);
                fma2(acc[i][1], xv, fv1);
            }
        }
        __syncthreads();
    }
#pragma unroll
    for (int i = 0; i < 4; i++) {
        const float2 r0 = unpack2(acc[i][0]);
        const float2 r1 = unpack2(acc[i][1]);
        const float2 v = make_float2(r0.x + r0.y, r1.x + r1.y);
        *(float2*)&g_A[(((size_t)b * 32 + cg + i) * 1024 + h) * 64 + fg] = v;
    }
}

// ---------------------------------------------------------------------------
// Stage B: partial X over a 256-h quarter.
// CTA per (hq,c,b).  X[k1i,k2] += A[h,k2] * e^{-2pi i k1 h / 1024}.
// Thread: k2 = t&31, 8 consecutive k1i.  acc packs (Xr,Xi).
// ---------------------------------------------------------------------------
__global__ void __launch_bounds__(256) kB() {
    const int hq = blockIdx.x, c = blockIdx.y, b = blockIdx.z;
    __shared__ __align__(16) float As[32 * 66];
    __shared__ __align__(16) float EB4s[32 * 256];
    const int t = threadIdx.x;
    const int k2 = t & 31, r = t >> 5;
    unsigned long long acc[8] = {};
    const float* abase = g_A + ((size_t)(b * 32 + c) * 1024 + hq * 256) * 64;

    for (int ch = 0; ch < 8; ch++) {
        const int h0c = hq * 256 + ch * 32;
#pragma unroll
        for (int k = 0; k < 4; k++) {                // 1024 float2
            const int idx = t + k * 256;
            const int row = idx >> 5, cp = (idx & 31) * 2;
            *(float2*)&As[row * 66 + cp] = *(const float2*)&abase[(ch * 32 + row) * 64 + cp];
        }
#pragma unroll
        for (int k = 0; k < 8; k++) {                // 2048 float4
            const int idx = t + k * 256;
            *(float4*)&EB4s[idx * 4] = *(const float4*)&g_EB4[h0c * 256 + idx * 4];
        }
        __syncthreads();
#pragma unroll 4
        for (int hh = 0; hh < 32; hh++) {
            const float2 a = *(const float2*)&As[hh * 66 + 2 * k2];
            const unsigned long long arr = pack2(a.x, a.x);
            const unsigned long long aii = pack2(a.y, a.y);
#pragma unroll
            for (int j = 0; j < 8; j++) {
                const ulonglong2 e = *(const ulonglong2*)&EB4s[(hh * 64 + r * 8 + j) * 4];
                fma2(acc[j], arr, e.x);
                fma2(acc[j], aii, e.y);
            }
        }
        __syncthreads();
    }
#pragma unroll
    for (int j = 0; j < 8; j++) {
        const int k1i = r * 8 + j;
        *(float2*)&g_Xp[(size_t)((((hq * 2 + b) * 32 + c) * 64 + k1i) * 32 + k2) * 2] =
            unpack2(acc[j]);
    }
}

// Reduce 4 h-quarter partials and apply combined weights.
__global__ void k_reduce_w() {
    const int id = blockIdx.x * 256 + threadIdx.x;   // 131072
    const int k2 = id & 31, k1i = (id >> 5) & 63, c = (id >> 11) & 31, b = id >> 16;
    float xr = 0.f, xi = 0.f;
#pragma unroll
    for (int hq = 0; hq < 4; hq++) {
        const float2 p = *(const float2*)
            &g_Xp[(size_t)((((hq * 2 + b) * 32 + c) * 64 + k1i) * 32 + k2) * 2];
        xr += p.x; xi += p.y;
    }
    const int wci = ((c << 6) + k1i) * 32 + k2;
    const float wr = g_Wc[wci * 2], wi = g_Wc[wci * 2 + 1];
    const float2 o = make_float2(xr * wr - xi * wi, xr * wi + xi * wr);
    *(float2*)&g_XW[((size_t)(b * 32 + c) * 64 + k1i) * 64 + 2 * k2] = o;
}

// ---------------------------------------------------------------------------
// Stage C: Z[b,h,c,2k2] = sum_{k1i} XW[b,c,k1i,k2] * e^{+2pi i k1 h/1024}/1024.
// CTA per (hb(16h), c, b).  Thread: k2 = t&31, 2 h values.
// ---------------------------------------------------------------------------
__global__ void __launch_bounds__(256) kC() {
    const int hb = blockIdx.x, c = blockIdx.y, b = blockIdx.z;
    const int h0 = hb * 16;
    __shared__ __align__(16) float XWs[64 * 64];
    __shared__ __align__(16) float EC4s[16 * 256];
    const int t = threadIdx.x;
#pragma unroll
    for (int k = 0; k < 8; k++) {                    // 2048 float2
        const int idx = t + k * 256;
        const int row = idx >> 5, cp = (idx & 31) * 2;
        *(float2*)&XWs[row * 64 + cp] =
            *(const float2*)&g_XW[((size_t)(b * 32 + c) * 64 + row) * 64 + cp];
    }
#pragma unroll
    for (int k = 0; k < 4; k++) {                    // 1024 float4
        const int idx = t + k * 256;
        *(float4*)&EC4s[idx * 4] = *(const float4*)&g_EC4[h0 * 256 + idx * 4];
    }
    __syncthreads();
    const int k2 = t & 31, r = t >> 5;
    unsigned long long acc[2] = {};
#pragma unroll 8
    for (int k1i = 0; k1i < 64; k1i++) {
        const float2 xw = *(const float2*)&XWs[k1i * 64 + 2 * k2];
        const unsigned long long xrr = pack2(xw.x, xw.x);
        const unsigned long long xii = pack2(xw.y, xw.y);
#pragma unroll
        for (int i = 0; i < 2; i++) {
            const ulonglong2 e = *(const ulonglong2*)&EC4s[((r * 2 + i) * 64 + k1i) * 4];
            fma2(acc[i], xrr, e.x);
            fma2(acc[i], xii, e.y);
        }
    }
#pragma unroll
    for (int i = 0; i < 2; i++) {
        const int h = h0 + r * 2 + i;
        *(float2*)&g_Z[(((size_t)b * 1024 + h) * 32 + c) * 64 + 2 * k2] = unpack2(acc[i]);
    }
}

// ---------------------------------------------------------------------------
// Stage D: y[b,h,w,c] = sum_fcol GD[w,fcol] * Z[b,h,c,fcol].
// CTA per (h,b).  M=1024(w) x N=32(c) x K=64, w-chunks of 128.
// Thread: 4 w x 4 c; f32x2 packs even/odd-fcol partial sums.
// ---------------------------------------------------------------------------
__global__ void __launch_bounds__(256) kD(float* __restrict__ y) {
    const int h = blockIdx.x, b = blockIdx.y;
    __shared__ __align__(16) float Zs[32 * 66];     // [c][fcol]
    __shared__ __align__(16) float Gs[128 * 66];    // [w][fcol]
    const int t = threadIdx.x;
    const int cg = (t & 7) * 4;
    const int wg = (t >> 3) * 4;
    const float* zb = g_Z + ((size_t)(b * 1024 + h)) * 32 * 64;
#pragma unroll
    for (int k = 0; k < 4; k++) {                    // 1024 float2
        const int idx = t + k * 256;
        const int row = idx >> 5, cp = (idx & 31) * 2;
        *(float2*)&Zs[row * 66 + cp] = *(const float2*)&zb[row * 64 + cp];
    }
    float* yb = y + ((size_t)(b * 1024 + h)) * 1024 * 32;

    for (int w0 = 0; w0 < 1024; w0 += 128) {
#pragma unroll
        for (int k = 0; k < 16; k++) {               // 4096 float2
            const int idx = t + k * 256;
            const int row = idx >> 5, cp = (idx & 31) * 2;
            *(float2*)&Gs[row * 66 + cp] = *(const float2*)&g_GD[(w0 + row) * 64 + cp];
        }
        __syncthreads();
        unsigned long long acc[4][4] = {};
#pragma unroll 8
        for (int fp = 0; fp < 32; fp++) {
            unsigned long long zv[4], gv[4];
#pragma unroll
            for (int i = 0; i < 4; i++)
                zv[i] = *(const unsigned long long*)&Zs[(cg + i) * 66 + 2 * fp];
#pragma unroll
            for (int i = 0; i < 4; i++)
                gv[i] = *(const unsigned long long*)&Gs[(wg + i) * 66 + 2 * fp];
#pragma unroll
            for (int wi = 0; wi < 4; wi++)
#pragma unroll
                for (int ci = 0; ci < 4; ci++)
                    fma2(acc[wi][ci], gv[wi], zv[ci]);
        }
#pragma unroll
        for (int wi = 0; wi < 4; wi++) {
            const float2 a0 = unpack2(acc[wi][0]);
            const float2 a1 = unpack2(acc[wi][1]);
            const float2 a2 = unpack2(acc[wi][2]);
            const float2 a3 = unpack2(acc[wi][3]);
            float4 o;
            o.x = a0.x + a0.y; o.y = a1.x + a1.y;
            o.z = a2.x + a2.y; o.w = a3.x + a3.y;
            *(float4*)&yb[(size_t)(w0 + wg + wi) * 32 + cg] = o;
        }
        __syncthreads();
    }
}

// ---------------------------------------------------------------------------
extern "C" void kernel_launch(void* const* d_in, const int* in_sizes, int n_in,
                              void* d_out, int out_size) {
    const float* x   = (const float*)d_in[0];
    const float* w0r = (const float*)d_in[1];
    const float* w0i = (const float*)d_in[2];
    const float* w1r = (const float*)d_in[3];
    const float* w1i = (const float*)d_in[4];
    const float* w2r = (const float*)d_in[5];
    const float* w2i = (const float*)d_in[6];
    float* y = (float*)d_out;

    k_init_tables<<<1024, 64>>>();
    k_init_w<<<256, 256>>>(w0r, w0i, w1r, w1i, w2r, w2i);
    kA<<<dim3(1024, 2), 256>>>(x);
    kB<<<dim3(4, 32, 2), 256>>>();
    k_reduce_w<<<512, 256>>>();
    kC<<<dim3(64, 32, 2), 256>>>();
    kD<<<dim3(1024, 2), 256>>>(y);
}

// round 9
// speedup vs baseline: 1.3445x; 1.3445x over previous
#include <cuda_runtime.h>
#include <cuda_bf16.h>
#include <cstdint>

// ---------------------------------------------------------------------------
// FNO spectral block: B=2, H=1024, W=1024, C=32, modes rows {0..31,992..1023},
// cols 0..31.  Four partial-DFT GEMM stages, fp32 via packed f32x2 FMA.
// Round 8 passed @1008us (LDS-bound).  This round: wide register tiles so the
// inner loops are FMA-bound (>=2.7 FFMA2 per LDS).
// ---------------------------------------------------------------------------

#define Bn 2
#define Hn 1024
#define Wn 1024
#define Cn 32

// ---- device scratch (allocation-free) ----
__device__ float g_FAT[64 * 1024];                  // [fcol][w]: 2k2 -> cos, 2k2+1 -> -sin
__device__ float g_GD [1024 * 64];                  // [w][fcol]: sc*cos, -sc*sin
__device__ float g_EB4[1024 * 64 * 4];              // [h][k1i]: (c,-s, s,c)   e^{-i th}
__device__ float g_EC4[1024 * 64 * 4];              // [h][k1i]: (c, s,-s,c)/H e^{+i th}/H
__device__ float g_Wc [32 * 64 * 32 * 2];           // combined w0*(w1|w2), complex
__device__ float g_A  [(size_t)Bn * Cn * Hn * 64];  // [b][c][h][fcol]
__device__ float g_Xp [8 * 32 * 64 * 32 * 2];       // [hq*2+b][c][k1i][k2] complex partials
__device__ float g_XW [(size_t)Bn * Cn * 64 * 64];  // [b][c][k1i][2k2]
__device__ float g_Z  [(size_t)Bn * Hn * Cn * 64];  // [b][h][c][fcol]

// ---- packed fp32x2 helpers ----
typedef unsigned long long ull;
__device__ __forceinline__ void fma2(ull& acc, ull a, ull b) {
    asm("fma.rn.f32x2 %0, %1, %2, %0;" : "+l"(acc) : "l"(a), "l"(b));
}
__device__ __forceinline__ ull pack2(float x, float y) {
    ull r;
    asm("mov.b64 %0, {%1, %2};" : "=l"(r) : "f"(x), "f"(y));
    return r;
}
__device__ __forceinline__ float2 unpack2(ull v) {
    float2 r;
    asm("mov.b64 {%0, %1}, %2;" : "=f"(r.x), "=f"(r.y) : "l"(v));
    return r;
}

// ---------------------------------------------------------------------------
// Twiddle tables.  Exact integer mod-1024 phase + double sincospi.
// ---------------------------------------------------------------------------
__global__ void k_init_tables() {
    const int row = blockIdx.x;     // w for FAT/GD, h for EB4/EC4
    const int t = threadIdx.x;      // 64
    if (t < 32) {
        const int k2 = t;
        const int r = (k2 * row) & 1023;
        double s, c;
        sincospi((double)r / 512.0, &s, &c);
        g_FAT[(2 * k2)     * 1024 + row] = (float)c;
        g_FAT[(2 * k2 + 1) * 1024 + row] = (float)(-s);
        const double sc = (k2 == 0 ? 1.0 : 2.0) / 1024.0;
        g_GD[row * 64 + 2 * k2]     = (float)(sc * c);
        g_GD[row * 64 + 2 * k2 + 1] = (float)(-sc * s);
    }
    {
        const int k1i = t;
        const int k1 = (k1i < 32) ? k1i : (960 + k1i);  // 992..1023
        const int r = (k1 * row) & 1023;
        double s, c;
        sincospi((double)r / 512.0, &s, &c);
        float* eb = &g_EB4[(row * 64 + k1i) * 4];
        eb[0] = (float)c;  eb[1] = (float)(-s);
        eb[2] = (float)s;  eb[3] = (float)c;
        const double inv = 1.0 / 1024.0;
        float* ec = &g_EC4[(row * 64 + k1i) * 4];
        ec[0] = (float)(c * inv);  ec[1] = (float)(s * inv);
        ec[2] = (float)(-s * inv); ec[3] = (float)(c * inv);
    }
}

// Combined weights Wc[c][k1i][k2] = w0[c] * (w1|w2)[c, m1, k2], complex.
__global__ void k_init_w(const float* __restrict__ w0r, const float* __restrict__ w0i,
                         const float* __restrict__ w1r, const float* __restrict__ w1i,
                         const float* __restrict__ w2r, const float* __restrict__ w2i) {
    const int idx = blockIdx.x * 256 + threadIdx.x;   // 65536
    const int k2 = idx & 31;
    const int k1i = (idx >> 5) & 63;
    const int c = idx >> 11;
    const float ar = w0r[c], ai = w0i[c];
    float br, bi;
    if (k1i < 32) {
        const int o = (c * 32 + k1i) * 32 + k2;
        br = w1r[o]; bi = w1i[o];
    } else {
        const int o = (c * 32 + (k1i - 32)) * 32 + k2;
        br = w2r[o]; bi = w2i[o];
    }
    g_Wc[idx * 2]     = ar * br - ai * bi;
    g_Wc[idx * 2 + 1] = ar * bi + ai * br;
}

// ---------------------------------------------------------------------------
// Stage A: A[b,c,h,fcol] = sum_w x[b,h,w,c] * FAT[fcol,w].
// CTA covers 2 h rows (shared F tile).  128 thr, thread tile 8c x 4f.
// Per w-pair: 8+4 LDS.64 per 32 FFMA2.
// ---------------------------------------------------------------------------
__global__ void __launch_bounds__(128) kA(const float* __restrict__ x) {
    const int hb = blockIdx.x;           // 0..511 (2 h per CTA)
    const int b = blockIdx.y;
    __shared__ __align__(16) float xs[2][32][66];   // [hg][c][w]
    __shared__ __align__(16) float FAs[64][66];     // [fcol][w]
    const int t = threadIdx.x;
    const int hg = t >> 6;
    const int tid6 = t & 63;
    const int c0 = (tid6 & 3) * 8;       // 4 c-groups x 8
    const int f0 = (tid6 >> 2) * 4;      // 16 f-groups x 4
    ull acc[8][4] = {};
    const float* xr0 = x + ((size_t)(b * 1024 + hb * 2)) * 32768;

    for (int w0 = 0; w0 < 1024; w0 += 64) {
        // xs: 2h x 64w x 32c transpose-load (1024 float4)
#pragma unroll
        for (int k = 0; k < 8; k++) {
            const int idx = t + k * 128;
            const int hs = idx >> 9;
            const int ww = (idx >> 3) & 63;
            const int c4 = (idx & 7) * 4;
            const float4 v = *(const float4*)&xr0[(size_t)hs * 32768 + (w0 + ww) * 32 + c4];
            xs[hs][c4 + 0][ww] = v.x;
            xs[hs][c4 + 1][ww] = v.y;
            xs[hs][c4 + 2][ww] = v.z;
            xs[hs][c4 + 3][ww] = v.w;
        }
        // FAs: 64 x 64 (2048 float2)
#pragma unroll
        for (int k = 0; k < 16; k++) {
            const int idx = t + k * 128;
            const int fr = idx >> 5;
            const int wp2 = (idx & 31) * 2;
            *(float2*)&FAs[fr][wp2] = *(const float2*)&g_FAT[fr * 1024 + w0 + wp2];
        }
        __syncthreads();
#pragma unroll 8
        for (int wp = 0; wp < 32; wp++) {
            ull fv[4];
#pragma unroll
            for (int j = 0; j < 4; j++)
                fv[j] = *(const ull*)&FAs[f0 + j][2 * wp];
#pragma unroll
            for (int i = 0; i < 8; i++) {
                const ull xv = *(const ull*)&xs[hg][c0 + i][2 * wp];
#pragma unroll
                for (int j = 0; j < 4; j++)
                    fma2(acc[i][j], xv, fv[j]);
            }
        }
        __syncthreads();
    }
    const int h = hb * 2 + hg;
#pragma unroll
    for (int i = 0; i < 8; i++) {
        float4 o;
        const float2 r0 = unpack2(acc[i][0]);
        const float2 r1 = unpack2(acc[i][1]);
        const float2 r2 = unpack2(acc[i][2]);
        const float2 r3 = unpack2(acc[i][3]);
        o.x = r0.x + r0.y; o.y = r1.x + r1.y;
        o.z = r2.x + r2.y; o.w = r3.x + r3.y;
        *(float4*)&g_A[(((size_t)b * 32 + c0 + i) * 1024 + h) * 64 + f0] = o;
    }
}

// ---------------------------------------------------------------------------
// Stage B: partial X over a 256-h quarter.  Complex GEMM M=64(k1i) N=32(k2)
// K=256(h).  128 thr, thread tile 4k1i x 4k2 (k1i lane-consecutive).
// Per h: 4 LDS.128(e) + 4 LDS.64(a) + 8 mov per 32 FFMA2.
// ---------------------------------------------------------------------------
__global__ void __launch_bounds__(128) kB() {
    const int hq = blockIdx.x, c = blockIdx.y, b = blockIdx.z;
    __shared__ __align__(16) float2 As[32][33];    // [hh][k2]
    __shared__ __align__(16) float4 EBs[32][64];   // [hh][k1i]
    const int t = threadIdx.x;
    const int k1l = t & 15;              // k1i = k1l + 16*i
    const int k2g = (t >> 4) * 4;        // 8 groups x 4
    ull acc[4][4] = {};
    const float* abase = g_A + ((size_t)(b * 32 + c) * 1024 + hq * 256) * 64;

    for (int ch = 0; ch < 8; ch++) {
        const int h0c = hq * 256 + ch * 32;
#pragma unroll
        for (int k = 0; k < 8; k++) {                 // 1024 float2
            const int idx = t + k * 128;
            const int hh = idx >> 5, k2 = idx & 31;
            As[hh][k2] = *(const float2*)&abase[(ch * 32 + hh) * 64 + 2 * k2];
        }
#pragma unroll
        for (int k = 0; k < 16; k++) {                // 2048 float4
            const int idx = t + k * 128;
            const int hh = idx >> 6, k1 = idx & 63;
            EBs[hh][k1] = *(const float4*)&g_EB4[((h0c + hh) * 64 + k1) * 4];
        }
        __syncthreads();
#pragma unroll 4
        for (int hh = 0; hh < 32; hh++) {
            ull ar[4], ai[4];
#pragma unroll
            for (int j = 0; j < 4; j++) {
                const float2 a = As[hh][k2g + j];
                ar[j] = pack2(a.x, a.x);
                ai[j] = pack2(a.y, a.y);
            }
#pragma unroll
            for (int i = 0; i < 4; i++) {
                const ulonglong2 e = *(const ulonglong2*)&EBs[hh][k1l + 16 * i];
#pragma unroll
                for (int j = 0; j < 4; j++) {
                    fma2(acc[i][j], ar[j], e.x);
                    fma2(acc[i][j], ai[j], e.y);
                }
            }
        }
        __syncthreads();
    }
#pragma unroll
    for (int i = 0; i < 4; i++) {
        const int k1i = k1l + 16 * i;
#pragma unroll
        for (int j = 0; j < 4; j++) {
            *(float2*)&g_Xp[(size_t)((((hq * 2 + b) * 32 + c) * 64 + k1i) * 32 + (k2g + j)) * 2]
                = unpack2(acc[i][j]);
        }
    }
}

// Reduce 4 h-quarter partials and apply combined weights.
__global__ void k_reduce_w() {
    const int id = blockIdx.x * 256 + threadIdx.x;   // 131072
    const int k2 = id & 31, k1i = (id >> 5) & 63, c = (id >> 11) & 31, b = id >> 16;
    float xr = 0.f, xi = 0.f;
#pragma unroll
    for (int hq = 0; hq < 4; hq++) {
        const float2 p = *(const float2*)
            &g_Xp[(size_t)((((hq * 2 + b) * 32 + c) * 64 + k1i) * 32 + k2) * 2];
        xr += p.x; xi += p.y;
    }
    const int wci = ((c << 6) + k1i) * 32 + k2;
    const float wr = g_Wc[wci * 2], wi = g_Wc[wci * 2 + 1];
    const float2 o = make_float2(xr * wr - xi * wi, xr * wi + xi * wr);
    *(float2*)&g_XW[((size_t)(b * 32 + c) * 64 + k1i) * 64 + 2 * k2] = o;
}

// ---------------------------------------------------------------------------
// Stage C: Z[b,h,c,2k2] = sum_{k1i} XW * e^{+i}/H.  Complex GEMM M=64h
// N=32k2 K=64k1i per (hc,c,b).  128 thr, tile 4h x 4k2, k1i-chunks of 16.
// ---------------------------------------------------------------------------
__global__ void __launch_bounds__(128) kC() {
    const int hc = blockIdx.x, c = blockIdx.y, b = blockIdx.z;
    const int h0 = hc * 64;
    __shared__ __align__(16) float2 XWs[64][33];   // [k1i][k2]
    __shared__ __align__(16) float4 ECs[64][17];   // [h][k1i-chunk], padded
    const int t = threadIdx.x;
    const int hl = t & 15;               // h = h0 + hl + 16*i
    const int k2g = (t >> 4) * 4;
    ull acc[4][4] = {};
#pragma unroll
    for (int k = 0; k < 16; k++) {                    // 2048 float2
        const int idx = t + k * 128;
        const int k1 = idx >> 5, k2 = idx & 31;
        XWs[k1][k2] = *(const float2*)&g_XW[((size_t)(b * 32 + c) * 64 + k1) * 64 + 2 * k2];
    }
    for (int kc = 0; kc < 4; kc++) {
        __syncthreads();
#pragma unroll
        for (int k = 0; k < 8; k++) {                 // 1024 float4
            const int idx = t + k * 128;
            const int hh = idx >> 4, kk = idx & 15;
            ECs[hh][kk] = *(const float4*)&g_EC4[((h0 + hh) * 64 + kc * 16 + kk) * 4];
        }
        __syncthreads();
#pragma unroll 4
        for (int kk = 0; kk < 16; kk++) {
            const int k1 = kc * 16 + kk;
            ull xr[4], xi[4];
#pragma unroll
            for (int j = 0; j < 4; j++) {
                const float2 xw = XWs[k1][k2g + j];
                xr[j] = pack2(xw.x, xw.x);
                xi[j] = pack2(xw.y, xw.y);
            }
#pragma unroll
            for (int i = 0; i < 4; i++) {
                const ulonglong2 e = *(const ulonglong2*)&ECs[hl + 16 * i][kk];
#pragma unroll
                for (int j = 0; j < 4; j++) {
                    fma2(acc[i][j], xr[j], e.x);
                    fma2(acc[i][j], xi[j], e.y);
                }
            }
        }
    }
#pragma unroll
    for (int i = 0; i < 4; i++) {
        const int h = h0 + hl + 16 * i;
#pragma unroll
        for (int j = 0; j < 4; j++) {
            *(float2*)&g_Z[(((size_t)b * 1024 + h) * 32 + c) * 64 + 2 * (k2g + j)]
                = unpack2(acc[i][j]);
        }
    }
}

// ---------------------------------------------------------------------------
// Stage D: y[b,h,w,c] = sum_fcol GD[w,fcol] * Z[b,h,c,fcol].
// CTA per (h,b), w-chunks of 128.  128 thr, tile 8w x 4c (w lane-consecutive).
// Per fcol-pair: 8+4 LDS.64 per 32 FFMA2.
// ---------------------------------------------------------------------------
__global__ void __launch_bounds__(128) kD(float* __restrict__ y) {
    const int h = blockIdx.x, b = blockIdx.y;
    __shared__ __align__(16) float Zs[32][68];     // [c][fcol]
    __shared__ __align__(16) float Gs[128][68];    // [w][fcol]
    const int t = threadIdx.x;
    const int wl = t & 15;               // w = w0 + wl + 16*i
    const int c0 = (t >> 4) * 4;         // 8 groups x 4
    const float* zb = g_Z + (size_t)(b * 1024 + h) * 2048;
#pragma unroll
    for (int k = 0; k < 4; k++) {                     // 512 float4
        const int idx = t + k * 128;
        const int row = idx >> 4, q = (idx & 15) * 4;
        *(float4*)&Zs[row][q] = *(const float4*)&zb[row * 64 + q];
    }
    float* yb = y + (size_t)(b * 1024 + h) * 32768;

    for (int w0 = 0; w0 < 1024; w0 += 128) {
#pragma unroll
        for (int k = 0; k < 16; k++) {                // 2048 float4
            const int idx = t + k * 128;
            const int row = idx >> 4, q = (idx & 15) * 4;
            *(float4*)&Gs[row][q] = *(const float4*)&g_GD[(w0 + row) * 64 + q];
        }
        __syncthreads();
        ull acc[8][4] = {};
#pragma unroll 8
        for (int fp = 0; fp < 32; fp++) {
            ull zv[4];
#pragma unroll
            for (int j = 0; j < 4; j++)
                zv[j] = *(const ull*)&Zs[c0 + j][2 * fp];
#pragma unroll
            for (int i = 0; i < 8; i++) {
                const ull gv = *(const ull*)&Gs[wl + 16 * i][2 * fp];
#pragma unroll
                for (int j = 0; j < 4; j++)
                    fma2(acc[i][j], gv, zv[j]);
            }
        }
#pragma unroll
        for (int i = 0; i < 8; i++) {
            const int w = w0 + wl + 16 * i;
            float4 o;
            const float2 a0 = unpack2(acc[i][0]);
            const float2 a1 = unpack2(acc[i][1]);
            const float2 a2 = unpack2(acc[i][2]);
            const float2 a3 = unpack2(acc[i][3]);
            o.x = a0.x + a0.y; o.y = a1.x + a1.y;
            o.z = a2.x + a2.y; o.w = a3.x + a3.y;
            *(float4*)&yb[(size_t)w * 32 + c0] = o;
        }
        __syncthreads();
    }
}

// ---------------------------------------------------------------------------
extern "C" void kernel_launch(void* const* d_in, const int* in_sizes, int n_in,
                              void* d_out, int out_size) {
    const float* x   = (const float*)d_in[0];
    const float* w0r = (const float*)d_in[1];
    const float* w0i = (const float*)d_in[2];
    const float* w1r = (const float*)d_in[3];
    const float* w1i = (const float*)d_in[4];
    const float* w2r = (const float*)d_in[5];
    const float* w2i = (const float*)d_in[6];
    float* y = (float*)d_out;

    k_init_tables<<<1024, 64>>>();
    k_init_w<<<256, 256>>>(w0r, w0i, w1r, w1i, w2r, w2i);
    kA<<<dim3(512, 2), 128>>>(x);
    kB<<<dim3(4, 32, 2), 128>>>();
    k_reduce_w<<<512, 256>>>();
    kC<<<dim3(16, 32, 2), 128>>>();
    kD<<<dim3(1024, 2), 128>>>(y);
}

// round 11
// speedup vs baseline: 3.0831x; 2.2931x over previous
#include <cuda_runtime.h>
#include <cuda_bf16.h>
#include <cstdint>

// ---------------------------------------------------------------------------
// FNO spectral block: B=2, H=1024, W=1024, C=32, modes rows {0..31,992..1023},
// cols 0..31.  Stages A/D: warp-level bf16 mma.sync (split-bf16 3-MMA).
// Stages B/C: fp32 f32x2 (proven in R9).  No 'a'-suffix PTX features used.
// ---------------------------------------------------------------------------

typedef unsigned long long ull;

// ---- device scratch (allocation-free) ----
__device__ float g_EB4[1024 * 64 * 4];               // [h][k1i]: (c,-s, s,c)
__device__ float g_EC4[1024 * 64 * 4];               // [h][k1i]: (c, s,-s,c)/H
__device__ float g_Wc [32 * 64 * 32 * 2];            // combined w0*(w1|w2)
__device__ __nv_bfloat16 g_FBh[64 * 1024];           // fwd DFT [fcol][w] bf16 hi
__device__ __nv_bfloat16 g_FBl[64 * 1024];           // fwd DFT lo
__device__ __nv_bfloat16 g_GDh[1024 * 64];           // inv DFT [w][fcol] bf16 hi
__device__ __nv_bfloat16 g_GDl[1024 * 64];           // inv DFT lo
__device__ float g_A  [(size_t)2 * 32 * 1024 * 64];  // [b][c][h][fcol]
__device__ float g_Xp [32 * 32 * 64 * 32 * 2];       // [hq*2+b][c][k1i][k2]
__device__ float g_XW [(size_t)2 * 32 * 64 * 64];    // [b][c][k1i][2k2]
__device__ float g_Z  [(size_t)2 * 1024 * 32 * 64];  // [b][h][c][fcol]

// ---- packed fp32x2 helpers (kB/kC) ----
__device__ __forceinline__ void fma2(ull& acc, ull a, ull b) {
    asm("fma.rn.f32x2 %0, %1, %2, %0;" : "+l"(acc) : "l"(a), "l"(b));
}
__device__ __forceinline__ ull pack2(float x, float y) {
    ull r; asm("mov.b64 %0, {%1, %2};" : "=l"(r) : "f"(x), "f"(y)); return r;
}
__device__ __forceinline__ float2 unpack2(ull v) {
    float2 r; asm("mov.b64 {%0, %1}, %2;" : "=f"(r.x), "=f"(r.y) : "l"(v)); return r;
}

// ---- mma.sync / ldmatrix helpers (sm_80-compatible; no 'a' features) ----
__device__ __forceinline__ uint32_t smem_u32(const void* p) {
    uint32_t a;
    asm("{ .reg .u64 t; cvta.to.shared.u64 t, %1; cvt.u32.u64 %0, t; }" : "=r"(a) : "l"(p));
    return a;
}
__device__ __forceinline__ void mma_bf16(float* d, const uint32_t* a, const uint32_t* b) {
    asm("mma.sync.aligned.m16n8k16.row.col.f32.bf16.bf16.f32 "
        "{%0,%1,%2,%3}, {%4,%5,%6,%7}, {%8,%9}, {%0,%1,%2,%3};"
        : "+f"(d[0]), "+f"(d[1]), "+f"(d[2]), "+f"(d[3])
        : "r"(a[0]), "r"(a[1]), "r"(a[2]), "r"(a[3]), "r"(b[0]), "r"(b[1]));
}
__device__ __forceinline__ void ldmx4(uint32_t* r, uint32_t addr) {
    asm volatile("ldmatrix.sync.aligned.m8n8.x4.shared.b16 {%0,%1,%2,%3}, [%4];"
                 : "=r"(r[0]), "=r"(r[1]), "=r"(r[2]), "=r"(r[3]) : "r"(addr));
}
// split fp32 -> bf16 hi + bf16 residual (packed pairs)
__device__ __forceinline__ void split2(float a, float b, uint32_t& hi, uint32_t& lo) {
    __nv_bfloat162 h = __float22bfloat162_rn(make_float2(a, b));
    const float2 hf = __bfloat1622float2(h);
    __nv_bfloat162 l = __float22bfloat162_rn(make_float2(a - hf.x, b - hf.y));
    hi = *(uint32_t*)&h;
    lo = *(uint32_t*)&l;
}

// ---------------------------------------------------------------------------
// Init: twiddle tables.  Exact integer mod-1024 phase + double sincospi.
// ---------------------------------------------------------------------------
__global__ void k_init_tables() {
    const int row = blockIdx.x;     // w (FB/GD) and h (EB/EC)
    const int t = threadIdx.x;      // 0..63
    {
        const int k2 = t >> 1;
        const int r = (k2 * row) & 1023;
        double s, c;
        sincospi((double)r / 512.0, &s, &c);
        const float vF = (t & 1) ? (float)(-s) : (float)c;
        const double sc = (k2 == 0 ? 1.0 : 2.0) / 1024.0;
        const float vG = (t & 1) ? (float)(-sc * s) : (float)(sc * c);
        const __nv_bfloat16 fh = __float2bfloat16(vF);
        g_FBh[t * 1024 + row] = fh;
        g_FBl[t * 1024 + row] = __float2bfloat16(vF - __bfloat162float(fh));
        const __nv_bfloat16 gh = __float2bfloat16(vG);
        g_GDh[row * 64 + t] = gh;
        g_GDl[row * 64 + t] = __float2bfloat16(vG - __bfloat162float(gh));
    }
    {
        const int k1i = t;
        const int k1 = (k1i < 32) ? k1i : (960 + k1i);
        const int r = (k1 * row) & 1023;
        double s, c;
        sincospi((double)r / 512.0, &s, &c);
        float* eb = &g_EB4[(row * 64 + k1i) * 4];
        eb[0] = (float)c;  eb[1] = (float)(-s);
        eb[2] = (float)s;  eb[3] = (float)c;
        const double inv = 1.0 / 1024.0;
        float* ec = &g_EC4[(row * 64 + k1i) * 4];
        ec[0] = (float)(c * inv);  ec[1] = (float)(s * inv);
        ec[2] = (float)(-s * inv); ec[3] = (float)(c * inv);
    }
}

__global__ void k_init_w(const float* __restrict__ w0r, const float* __restrict__ w0i,
                         const float* __restrict__ w1r, const float* __restrict__ w1i,
                         const float* __restrict__ w2r, const float* __restrict__ w2i) {
    const int idx = blockIdx.x * 256 + threadIdx.x;   // 65536
    const int k2 = idx & 31;
    const int k1i = (idx >> 5) & 63;
    const int c = idx >> 11;
    const float ar = w0r[c], ai = w0i[c];
    float br, bi;
    if (k1i < 32) { const int o = (c * 32 + k1i) * 32 + k2;        br = w1r[o]; bi = w1i[o]; }
    else          { const int o = (c * 32 + (k1i - 32)) * 32 + k2; br = w2r[o]; bi = w2i[o]; }
    g_Wc[idx * 2]     = ar * br - ai * bi;
    g_Wc[idx * 2 + 1] = ar * bi + ai * br;
}

// ---------------------------------------------------------------------------
// Stage A (HMMA): CTA per (4h, b).  D[m=(hh,c)=128, n=fcol=64] =
//   sum_w x[h,w,c] * F[fcol,w].  K=1024 in 16 chunks of 64, split-bf16 x3.
// smem rows padded to 72 bf16 (144B) -> conflict-free ldmatrix.
// Warp = one h row (m-rows 32w..32w+31).
// ---------------------------------------------------------------------------
#define XH_OFF 0
#define XL_OFF 18432
#define FH_OFF 36864
#define FL_OFF 46080
#define SMEM_KTA 55296

__global__ void __launch_bounds__(128) kTA(const float* __restrict__ x) {
    extern __shared__ __align__(16) char sm[];
    char* XH = sm + XH_OFF;  char* XL = sm + XL_OFF;
    char* FH = sm + FH_OFF;  char* FL = sm + FL_OFF;
    const uint32_t sb = smem_u32(sm);
    const int hg = blockIdx.x, b = blockIdx.y;
    const int t = threadIdx.x, warp = t >> 5, lane = t & 31;
    const int h0 = hg * 4;
    const float* xb = x + (size_t)(b * 1024 + h0) * 32768;

    // per-lane ldmatrix tile-row offsets (m16n8k16 fragment arrangement)
    const int g = lane >> 3, r = lane & 7;
    const int a_m = ((g & 1) << 3) + r;      // A: +M0+16*t2
    const int a_k = (g >> 1) << 3;           //    +K0
    const int b_n = ((g >> 1) << 3) + r;     // B: +N0
    const int b_k = (g & 1) << 3;            //    +K0

    float acc[2][8][4];
#pragma unroll
    for (int i = 0; i < 2; i++)
#pragma unroll
        for (int j = 0; j < 8; j++)
#pragma unroll
            for (int q = 0; q < 4; q++) acc[i][j][q] = 0.f;

    const int M0 = warp * 32;
    for (int kc = 0; kc < 16; kc++) {
        const int w0 = kc * 64;
        __syncthreads();
        // X: 4h x 64w x 32c -> split bf16 [m=(hh,c)][k=w], pairs of w packed
#pragma unroll
        for (int j = 0; j < 8; j++) {
            const int idx = t + j * 128;
            const int c4 = idx & 7, wp = (idx >> 3) & 31, hh = idx >> 8;
            const float* p = xb + (size_t)hh * 32768 + (size_t)(w0 + 2 * wp) * 32 + c4 * 4;
            const float4 v0 = *(const float4*)p;
            const float4 v1 = *(const float4*)(p + 32);
            const float e0[4] = {v0.x, v0.y, v0.z, v0.w};
            const float e1[4] = {v1.x, v1.y, v1.z, v1.w};
#pragma unroll
            for (int i = 0; i < 4; i++) {
                const int m = hh * 32 + c4 * 4 + i;
                const int off = m * 144 + wp * 4;
                uint32_t hv, lv;
                split2(e0[i], e1[i], hv, lv);
                *(uint32_t*)(XH + off) = hv;
                *(uint32_t*)(XL + off) = lv;
            }
        }
        // F: 64 rows x 64 k (128B/row), hi + lo
#pragma unroll
        for (int j = 0; j < 4; j++) {
            const int idx = t + j * 128;
            const int f = idx >> 3, q = idx & 7;
            const int off = f * 144 + q * 16;
            *(uint4*)(FH + off) = *(const uint4*)&g_FBh[f * 1024 + w0 + q * 8];
            *(uint4*)(FL + off) = *(const uint4*)&g_FBl[f * 1024 + w0 + q * 8];
        }
        __syncthreads();
#pragma unroll
        for (int ks = 0; ks < 4; ks++) {
            const int K0 = ks * 16;
            uint32_t ah[2][4], al[2][4];
#pragma unroll
            for (int t2 = 0; t2 < 2; t2++) {
                const uint32_t ra =
                    sb + (uint32_t)((M0 + 16 * t2 + a_m) * 144 + (K0 + a_k) * 2);
                ldmx4(ah[t2], ra + XH_OFF);
                ldmx4(al[t2], ra + XL_OFF);
            }
#pragma unroll
            for (int jn = 0; jn < 4; jn++) {      // two n8 tiles per ldmx4
                const uint32_t rb =
                    sb + (uint32_t)((jn * 16 + b_n) * 144 + (K0 + b_k) * 2);
                uint32_t bh[4], bl[4];
                ldmx4(bh, rb + FH_OFF);
                ldmx4(bl, rb + FL_OFF);
#pragma unroll
                for (int t2 = 0; t2 < 2; t2++) {
                    mma_bf16(acc[t2][2 * jn],     ah[t2], bh);
                    mma_bf16(acc[t2][2 * jn],     ah[t2], bl);
                    mma_bf16(acc[t2][2 * jn],     al[t2], bh);
                    mma_bf16(acc[t2][2 * jn + 1], ah[t2], bh + 2);
                    mma_bf16(acc[t2][2 * jn + 1], ah[t2], bl + 2);
                    mma_bf16(acc[t2][2 * jn + 1], al[t2], bh + 2);
                }
            }
        }
    }
    // write A[b][c][h][f];  d0,d1: (m=cq, n=f2,f2+1), d2,d3: m+8
    const int h = h0 + warp;
    const int cq = lane >> 2, f2 = (lane & 3) * 2;
#pragma unroll
    for (int t2 = 0; t2 < 2; t2++)
#pragma unroll
        for (int j = 0; j < 8; j++) {
            const int c = 16 * t2 + cq;
            const int f = 8 * j + f2;
            *(float2*)&g_A[(((size_t)b * 32 + c) * 1024 + h) * 64 + f] =
                make_float2(acc[t2][j][0], acc[t2][j][1]);
            *(float2*)&g_A[(((size_t)b * 32 + c + 8) * 1024 + h) * 64 + f] =
                make_float2(acc[t2][j][2], acc[t2][j][3]);
        }
}

// ---------------------------------------------------------------------------
// Stage B (fp32): partial X over a 64-h slice.  grid (16,32,2).
// ---------------------------------------------------------------------------
__global__ void __launch_bounds__(128) kB() {
    const int hq = blockIdx.x, c = blockIdx.y, b = blockIdx.z;
    __shared__ __align__(16) float2 As[32][33];
    __shared__ __align__(16) float4 EBs[32][64];
    const int t = threadIdx.x;
    const int k1l = t & 15;
    const int k2g = (t >> 4) * 4;
    ull acc[4][4] = {};
    const float* abase = g_A + ((size_t)(b * 32 + c) * 1024 + hq * 64) * 64;

    for (int ch = 0; ch < 2; ch++) {
        const int h0c = hq * 64 + ch * 32;
#pragma unroll
        for (int k = 0; k < 8; k++) {
            const int idx = t + k * 128;
            const int hh = idx >> 5, k2 = idx & 31;
            As[hh][k2] = *(const float2*)&abase[(ch * 32 + hh) * 64 + 2 * k2];
        }
#pragma unroll
        for (int k = 0; k < 16; k++) {
            const int idx = t + k * 128;
            const int hh = idx >> 6, k1 = idx & 63;
            EBs[hh][k1] = *(const float4*)&g_EB4[((h0c + hh) * 64 + k1) * 4];
        }
        __syncthreads();
#pragma unroll 4
        for (int hh = 0; hh < 32; hh++) {
            ull ar[4], ai[4];
#pragma unroll
            for (int j = 0; j < 4; j++) {
                const float2 a = As[hh][k2g + j];
                ar[j] = pack2(a.x, a.x);
                ai[j] = pack2(a.y, a.y);
            }
#pragma unroll
            for (int i = 0; i < 4; i++) {
                const ulonglong2 e = *(const ulonglong2*)&EBs[hh][k1l + 16 * i];
#pragma unroll
                for (int j = 0; j < 4; j++) { fma2(acc[i][j], ar[j], e.x); fma2(acc[i][j], ai[j], e.y); }
            }
        }
        __syncthreads();
    }
#pragma unroll
    for (int i = 0; i < 4; i++) {
        const int k1i = k1l + 16 * i;
#pragma unroll
        for (int j = 0; j < 4; j++)
            *(float2*)&g_Xp[(size_t)((((hq * 2 + b) * 32 + c) * 64 + k1i) * 32 + (k2g + j)) * 2]
                = unpack2(acc[i][j]);
    }
}

// Reduce 16 h-slice partials and apply combined weights.
__global__ void k_reduce_w() {
    const int id = blockIdx.x * 256 + threadIdx.x;   // 131072
    const int k2 = id & 31, k1i = (id >> 5) & 63, c = (id >> 11) & 31, b = id >> 16;
    float xr = 0.f, xi = 0.f;
#pragma unroll
    for (int hq = 0; hq < 16; hq++) {
        const float2 p = *(const float2*)
            &g_Xp[(size_t)((((hq * 2 + b) * 32 + c) * 64 + k1i) * 32 + k2) * 2];
        xr += p.x; xi += p.y;
    }
    const int wci = ((c << 6) + k1i) * 32 + k2;
    const float wr = g_Wc[wci * 2], wi = g_Wc[wci * 2 + 1];
    const float2 o = make_float2(xr * wr - xi * wi, xr * wi + xi * wr);
    *(float2*)&g_XW[((size_t)(b * 32 + c) * 64 + k1i) * 64 + 2 * k2] = o;
}

// ---------------------------------------------------------------------------
// Stage C (fp32): Z expansion.  grid (32,32,2), 32 h per CTA.
// ---------------------------------------------------------------------------
__global__ void __launch_bounds__(128) kC() {
    const int hc = blockIdx.x, c = blockIdx.y, b = blockIdx.z;
    const int h0 = hc * 32;
    __shared__ __align__(16) float2 XWs[64][33];
    __shared__ __align__(16) float4 ECs[32][17];
    const int t = threadIdx.x;
    const int hl = t & 15;
    const int k2g = (t >> 4) * 4;
    ull acc[2][4] = {};
#pragma unroll
    for (int k = 0; k < 16; k++) {
        const int idx = t + k * 128;
        const int k1 = idx >> 5, k2 = idx & 31;
        XWs[k1][k2] = *(const float2*)&g_XW[((size_t)(b * 32 + c) * 64 + k1) * 64 + 2 * k2];
    }
    for (int kc = 0; kc < 4; kc++) {
        __syncthreads();
#pragma unroll
        for (int k = 0; k < 4; k++) {
            const int idx = t + k * 128;
            const int hh = idx >> 4, kk = idx & 15;
            ECs[hh][kk] = *(const float4*)&g_EC4[((h0 + hh) * 64 + kc * 16 + kk) * 4];
        }
        __syncthreads();
#pragma unroll 4
        for (int kk = 0; kk < 16; kk++) {
            const int k1 = kc * 16 + kk;
            ull xr[4], xi[4];
#pragma unroll
            for (int j = 0; j < 4; j++) {
                const float2 xw = XWs[k1][k2g + j];
                xr[j] = pack2(xw.x, xw.x);
                xi[j] = pack2(xw.y, xw.y);
            }
#pragma unroll
            for (int i = 0; i < 2; i++) {
                const ulonglong2 e = *(const ulonglong2*)&ECs[hl + 16 * i][kk];
#pragma unroll
                for (int j = 0; j < 4; j++) { fma2(acc[i][j], xr[j], e.x); fma2(acc[i][j], xi[j], e.y); }
            }
        }
    }
#pragma unroll
    for (int i = 0; i < 2; i++) {
        const int h = h0 + hl + 16 * i;
#pragma unroll
        for (int j = 0; j < 4; j++)
            *(float2*)&g_Z[(((size_t)b * 1024 + h) * 32 + c) * 64 + 2 * (k2g + j)]
                = unpack2(acc[i][j]);
    }
}

// ---------------------------------------------------------------------------
// Stage D (HMMA): CTA per (wb=128w, hg=32h, b).  Per h:
//   y[m=w=128, n=c=32] = sum_f GD[w,f] * Z[c,f], K=64, split-bf16 x3.
// GD fragments hoisted out of the h loop.
// ---------------------------------------------------------------------------
__global__ void __launch_bounds__(128) kTD(float* __restrict__ y) {
    __shared__ __align__(16) char GH[18432];
    __shared__ __align__(16) char GL[18432];
    __shared__ __align__(16) char ZH[4608];
    __shared__ __align__(16) char ZL[4608];
    const uint32_t GHb = smem_u32(GH), GLb = smem_u32(GL);
    const uint32_t ZHb = smem_u32(ZH), ZLb = smem_u32(ZL);
    const int wb = blockIdx.x, hg = blockIdx.y, b = blockIdx.z;
    const int t = threadIdx.x, warp = t >> 5, lane = t & 31;

    const int g = lane >> 3, r = lane & 7;
    const int a_m = ((g & 1) << 3) + r;
    const int a_k = (g >> 1) << 3;
    const int b_n = ((g >> 1) << 3) + r;
    const int b_k = (g & 1) << 3;

    // GD tile: 128 w-rows x 64 f (hi+lo)
#pragma unroll
    for (int j = 0; j < 8; j++) {
        const int idx = t + j * 128;
        const int row = idx >> 3, q = idx & 7;
        const int off = row * 144 + q * 16;
        *(uint4*)(GH + off) = *(const uint4*)&g_GDh[(wb * 128 + row) * 64 + q * 8];
        *(uint4*)(GL + off) = *(const uint4*)&g_GDl[(wb * 128 + row) * 64 + q * 8];
    }
    __syncthreads();

    // hoisted GD fragments: [ks][t2][4]
    const int M0 = warp * 32;
    uint32_t gh[4][2][4], gl[4][2][4];
#pragma unroll
    for (int ks = 0; ks < 4; ks++)
#pragma unroll
        for (int t2 = 0; t2 < 2; t2++) {
            const uint32_t off =
                (uint32_t)((M0 + 16 * t2 + a_m) * 144 + (ks * 16 + a_k) * 2);
            ldmx4(gh[ks][t2], GHb + off);
            ldmx4(gl[ks][t2], GLb + off);
        }

    const int cq = lane >> 2, f2 = (lane & 3) * 2;
    for (int hh = 0; hh < 32; hh++) {
        const int h = hg * 32 + hh;
        const float* zp = &g_Z[(size_t)(b * 1024 + h) * 2048];
        __syncthreads();    // prev iteration's ldmatrix reads of Z done
        // Z: 32c x 64f -> split bf16 [n=c][k=f]
#pragma unroll
        for (int j = 0; j < 8; j++) {
            const int idx = t + j * 128;
            const int c = idx >> 5, fp = idx & 31;
            const float2 zv = *(const float2*)&zp[c * 64 + 2 * fp];
            const int off = c * 144 + fp * 4;
            uint32_t hv, lv;
            split2(zv.x, zv.y, hv, lv);
            *(uint32_t*)(ZH + off) = hv;
            *(uint32_t*)(ZL + off) = lv;
        }
        __syncthreads();
        float acc[2][4][4];
#pragma unroll
        for (int i = 0; i < 2; i++)
#pragma unroll
            for (int j = 0; j < 4; j++)
#pragma unroll
                for (int q = 0; q < 4; q++) acc[i][j][q] = 0.f;
#pragma unroll
        for (int ks = 0; ks < 4; ks++) {
#pragma unroll
            for (int jn = 0; jn < 2; jn++) {
                const uint32_t off =
                    (uint32_t)((jn * 16 + b_n) * 144 + (ks * 16 + b_k) * 2);
                uint32_t bh[4], bl[4];
                ldmx4(bh, ZHb + off);
                ldmx4(bl, ZLb + off);
#pragma unroll
                for (int t2 = 0; t2 < 2; t2++) {
                    mma_bf16(acc[t2][2 * jn],     gh[ks][t2], bh);
                    mma_bf16(acc[t2][2 * jn],     gh[ks][t2], bl);
                    mma_bf16(acc[t2][2 * jn],     gl[ks][t2], bh);
                    mma_bf16(acc[t2][2 * jn + 1], gh[ks][t2], bh + 2);
                    mma_bf16(acc[t2][2 * jn + 1], gh[ks][t2], bl + 2);
                    mma_bf16(acc[t2][2 * jn + 1], gl[ks][t2], bh + 2);
                }
            }
        }
        // write y[b,h,w,c]
        float* yb = y + (size_t)(b * 1024 + h) * 32768;
#pragma unroll
        for (int t2 = 0; t2 < 2; t2++)
#pragma unroll
            for (int j = 0; j < 4; j++) {
                const int w = wb * 128 + M0 + 16 * t2 + cq;
                const int c = 8 * j + f2;
                *(float2*)&yb[(size_t)w * 32 + c] =
                    make_float2(acc[t2][j][0], acc[t2][j][1]);
                *(float2*)&yb[(size_t)(w + 8) * 32 + c] =
                    make_float2(acc[t2][j][2], acc[t2][j][3]);
            }
    }
}

// ---------------------------------------------------------------------------
extern "C" void kernel_launch(void* const* d_in, const int* in_sizes, int n_in,
                              void* d_out, int out_size) {
    const float* x   = (const float*)d_in[0];
    const float* w0r = (const float*)d_in[1];
    const float* w0i = (const float*)d_in[2];
    const float* w1r = (const float*)d_in[3];
    const float* w1i = (const float*)d_in[4];
    const float* w2r = (const float*)d_in[5];
    const float* w2i = (const float*)d_in[6];
    float* y = (float*)d_out;

    cudaFuncSetAttribute(kTA, cudaFuncAttributeMaxDynamicSharedMemorySize, SMEM_KTA);

    k_init_tables<<<1024, 64>>>();
    k_init_w<<<256, 256>>>(w0r, w0i, w1r, w1i, w2r, w2i);
    kTA<<<dim3(256, 2), 128, SMEM_KTA>>>(x);
    kB<<<dim3(16, 32, 2), 128>>>();
    k_reduce_w<<<512, 256>>>();
    kC<<<dim3(32, 32, 2), 128>>>();
    kTD<<<dim3(8, 32, 2), 128>>>(y);
}

// round 12
// speedup vs baseline: 3.0858x; 1.0009x over previous
#include <cuda_runtime.h>
#include <cuda_bf16.h>
#include <cstdint>

// ---------------------------------------------------------------------------
// FNO spectral block: B=2, H=1024, W=1024, C=32, modes rows {0..31,992..1023},
// cols 0..31.  Stages A/D: warp-level bf16 mma.sync (split-bf16 3-MMA).
// Stages B/C: fp32 f32x2 (proven in R9).  No 'a'-suffix PTX features used.
// ---------------------------------------------------------------------------

typedef unsigned long long ull;

// ---- device scratch (allocation-free) ----
__device__ float g_EB4[1024 * 64 * 4];               // [h][k1i]: (c,-s, s,c)
__device__ float g_EC4[1024 * 64 * 4];               // [h][k1i]: (c, s,-s,c)/H
__device__ float g_Wc [32 * 64 * 32 * 2];            // combined w0*(w1|w2)
__device__ __nv_bfloat16 g_FBh[64 * 1024];           // fwd DFT [fcol][w] bf16 hi
__device__ __nv_bfloat16 g_FBl[64 * 1024];           // fwd DFT lo
__device__ __nv_bfloat16 g_GDh[1024 * 64];           // inv DFT [w][fcol] bf16 hi
__device__ __nv_bfloat16 g_GDl[1024 * 64];           // inv DFT lo
__device__ float g_A  [(size_t)2 * 32 * 1024 * 64];  // [b][c][h][fcol]
__device__ float g_Xp [32 * 32 * 64 * 32 * 2];       // [hq*2+b][c][k1i][k2]
__device__ float g_XW [(size_t)2 * 32 * 64 * 64];    // [b][c][k1i][2k2]
__device__ float g_Z  [(size_t)2 * 1024 * 32 * 64];  // [b][h][c][fcol]

// ---- packed fp32x2 helpers (kB/kC) ----
__device__ __forceinline__ void fma2(ull& acc, ull a, ull b) {
    asm("fma.rn.f32x2 %0, %1, %2, %0;" : "+l"(acc) : "l"(a), "l"(b));
}
__device__ __forceinline__ ull pack2(float x, float y) {
    ull r; asm("mov.b64 %0, {%1, %2};" : "=l"(r) : "f"(x), "f"(y)); return r;
}
__device__ __forceinline__ float2 unpack2(ull v) {
    float2 r; asm("mov.b64 {%0, %1}, %2;" : "=f"(r.x), "=f"(r.y) : "l"(v)); return r;
}

// ---- mma.sync / ldmatrix helpers (sm_80-compatible; no 'a' features) ----
__device__ __forceinline__ uint32_t smem_u32(const void* p) {
    uint32_t a;
    asm("{ .reg .u64 t; cvta.to.shared.u64 t, %1; cvt.u32.u64 %0, t; }" : "=r"(a) : "l"(p));
    return a;
}
__device__ __forceinline__ void mma_bf16(float* d, const uint32_t* a, const uint32_t* b) {
    asm("mma.sync.aligned.m16n8k16.row.col.f32.bf16.bf16.f32 "
        "{%0,%1,%2,%3}, {%4,%5,%6,%7}, {%8,%9}, {%0,%1,%2,%3};"
        : "+f"(d[0]), "+f"(d[1]), "+f"(d[2]), "+f"(d[3])
        : "r"(a[0]), "r"(a[1]), "r"(a[2]), "r"(a[3]), "r"(b[0]), "r"(b[1]));
}
__device__ __forceinline__ void ldmx4(uint32_t* r, uint32_t addr) {
    asm volatile("ldmatrix.sync.aligned.m8n8.x4.shared.b16 {%0,%1,%2,%3}, [%4];"
                 : "=r"(r[0]), "=r"(r[1]), "=r"(r[2]), "=r"(r[3]) : "r"(addr));
}
// split fp32 -> bf16 hi + bf16 residual (packed pairs)
__device__ __forceinline__ void split2(float a, float b, uint32_t& hi, uint32_t& lo) {
    __nv_bfloat162 h = __float22bfloat162_rn(make_float2(a, b));
    const float2 hf = __bfloat1622float2(h);
    __nv_bfloat162 l = __float22bfloat162_rn(make_float2(a - hf.x, b - hf.y));
    hi = *(uint32_t*)&h;
    lo = *(uint32_t*)&l;
}

// ---------------------------------------------------------------------------
// Init: twiddle tables.  Exact integer mod-1024 phase + double sincospi.
// ---------------------------------------------------------------------------
__global__ void k_init_tables() {
    const int row = blockIdx.x;     // w (FB/GD) and h (EB/EC)
    const int t = threadIdx.x;      // 0..63
    {
        const int k2 = t >> 1;
        const int r = (k2 * row) & 1023;
        double s, c;
        sincospi((double)r / 512.0, &s, &c);
        const float vF = (t & 1) ? (float)(-s) : (float)c;
        const double sc = (k2 == 0 ? 1.0 : 2.0) / 1024.0;
        const float vG = (t & 1) ? (float)(-sc * s) : (float)(sc * c);
        const __nv_bfloat16 fh = __float2bfloat16(vF);
        g_FBh[t * 1024 + row] = fh;
        g_FBl[t * 1024 + row] = __float2bfloat16(vF - __bfloat162float(fh));
        const __nv_bfloat16 gh = __float2bfloat16(vG);
        g_GDh[row * 64 + t] = gh;
        g_GDl[row * 64 + t] = __float2bfloat16(vG - __bfloat162float(gh));
    }
    {
        const int k1i = t;
        const int k1 = (k1i < 32) ? k1i : (960 + k1i);
        const int r = (k1 * row) & 1023;
        double s, c;
        sincospi((double)r / 512.0, &s, &c);
        float* eb = &g_EB4[(row * 64 + k1i) * 4];
        eb[0] = (float)c;  eb[1] = (float)(-s);
        eb[2] = (float)s;  eb[3] = (float)c;
        const double inv = 1.0 / 1024.0;
        float* ec = &g_EC4[(row * 64 + k1i) * 4];
        ec[0] = (float)(c * inv);  ec[1] = (float)(s * inv);
        ec[2] = (float)(-s * inv); ec[3] = (float)(c * inv);
    }
}

__global__ void k_init_w(const float* __restrict__ w0r, const float* __restrict__ w0i,
                         const float* __restrict__ w1r, const float* __restrict__ w1i,
                         const float* __restrict__ w2r, const float* __restrict__ w2i) {
    const int idx = blockIdx.x * 256 + threadIdx.x;   // 65536
    const int k2 = idx & 31;
    const int k1i = (idx >> 5) & 63;
    const int c = idx >> 11;
    const float ar = w0r[c], ai = w0i[c];
    float br, bi;
    if (k1i < 32) { const int o = (c * 32 + k1i) * 32 + k2;        br = w1r[o]; bi = w1i[o]; }
    else          { const int o = (c * 32 + (k1i - 32)) * 32 + k2; br = w2r[o]; bi = w2i[o]; }
    g_Wc[idx * 2]     = ar * br - ai * bi;
    g_Wc[idx * 2 + 1] = ar * bi + ai * br;
}

// ---------------------------------------------------------------------------
// Stage A (HMMA): CTA per (4h, b).  D[m=(hh,c)=128, n=fcol=64] =
//   sum_w x[h,w,c] * F[fcol,w].  K=1024 in 16 chunks of 64, split-bf16 x3.
// smem rows padded to 72 bf16 (144B) -> conflict-free ldmatrix.
// Warp = one h row (m-rows 32w..32w+31).
// ---------------------------------------------------------------------------
#define XH_OFF 0
#define XL_OFF 18432
#define FH_OFF 36864
#define FL_OFF 46080
#define SMEM_KTA 55296

__global__ void __launch_bounds__(128) kTA(const float* __restrict__ x) {
    extern __shared__ __align__(16) char sm[];
    char* XH = sm + XH_OFF;  char* XL = sm + XL_OFF;
    char* FH = sm + FH_OFF;  char* FL = sm + FL_OFF;
    const uint32_t sb = smem_u32(sm);
    const int hg = blockIdx.x, b = blockIdx.y;
    const int t = threadIdx.x, warp = t >> 5, lane = t & 31;
    const int h0 = hg * 4;
    const float* xb = x + (size_t)(b * 1024 + h0) * 32768;

    // per-lane ldmatrix tile-row offsets (m16n8k16 fragment arrangement)
    const int g = lane >> 3, r = lane & 7;
    const int a_m = ((g & 1) << 3) + r;      // A: +M0+16*t2
    const int a_k = (g >> 1) << 3;           //    +K0
    const int b_n = ((g >> 1) << 3) + r;     // B: +N0
    const int b_k = (g & 1) << 3;            //    +K0

    float acc[2][8][4];
#pragma unroll
    for (int i = 0; i < 2; i++)
#pragma unroll
        for (int j = 0; j < 8; j++)
#pragma unroll
            for (int q = 0; q < 4; q++) acc[i][j][q] = 0.f;

    const int M0 = warp * 32;
    for (int kc = 0; kc < 16; kc++) {
        const int w0 = kc * 64;
        __syncthreads();
        // X: 4h x 64w x 32c -> split bf16 [m=(hh,c)][k=w], pairs of w packed
#pragma unroll
        for (int j = 0; j < 8; j++) {
            const int idx = t + j * 128;
            const int c4 = idx & 7, wp = (idx >> 3) & 31, hh = idx >> 8;
            const float* p = xb + (size_t)hh * 32768 + (size_t)(w0 + 2 * wp) * 32 + c4 * 4;
            const float4 v0 = *(const float4*)p;
            const float4 v1 = *(const float4*)(p + 32);
            const float e0[4] = {v0.x, v0.y, v0.z, v0.w};
            const float e1[4] = {v1.x, v1.y, v1.z, v1.w};
#pragma unroll
            for (int i = 0; i < 4; i++) {
                const int m = hh * 32 + c4 * 4 + i;
                const int off = m * 144 + wp * 4;
                uint32_t hv, lv;
                split2(e0[i], e1[i], hv, lv);
                *(uint32_t*)(XH + off) = hv;
                *(uint32_t*)(XL + off) = lv;
            }
        }
        // F: 64 rows x 64 k (128B/row), hi + lo
#pragma unroll
        for (int j = 0; j < 4; j++) {
            const int idx = t + j * 128;
            const int f = idx >> 3, q = idx & 7;
            const int off = f * 144 + q * 16;
            *(uint4*)(FH + off) = *(const uint4*)&g_FBh[f * 1024 + w0 + q * 8];
            *(uint4*)(FL + off) = *(const uint4*)&g_FBl[f * 1024 + w0 + q * 8];
        }
        __syncthreads();
#pragma unroll
        for (int ks = 0; ks < 4; ks++) {
            const int K0 = ks * 16;
            uint32_t ah[2][4], al[2][4];
#pragma unroll
            for (int t2 = 0; t2 < 2; t2++) {
                const uint32_t ra =
                    sb + (uint32_t)((M0 + 16 * t2 + a_m) * 144 + (K0 + a_k) * 2);
                ldmx4(ah[t2], ra + XH_OFF);
                ldmx4(al[t2], ra + XL_OFF);
            }
#pragma unroll
            for (int jn = 0; jn < 4; jn++) {      // two n8 tiles per ldmx4
                const uint32_t rb =
                    sb + (uint32_t)((jn * 16 + b_n) * 144 + (K0 + b_k) * 2);
                uint32_t bh[4], bl[4];
                ldmx4(bh, rb + FH_OFF);
                ldmx4(bl, rb + FL_OFF);
#pragma unroll
                for (int t2 = 0; t2 < 2; t2++) {
                    mma_bf16(acc[t2][2 * jn],     ah[t2], bh);
                    mma_bf16(acc[t2][2 * jn],     ah[t2], bl);
                    mma_bf16(acc[t2][2 * jn],     al[t2], bh);
                    mma_bf16(acc[t2][2 * jn + 1], ah[t2], bh + 2);
                    mma_bf16(acc[t2][2 * jn + 1], ah[t2], bl + 2);
                    mma_bf16(acc[t2][2 * jn + 1], al[t2], bh + 2);
                }
            }
        }
    }
    // write A[b][c][h][f];  d0,d1: (m=cq, n=f2,f2+1), d2,d3: m+8
    const int h = h0 + warp;
    const int cq = lane >> 2, f2 = (lane & 3) * 2;
#pragma unroll
    for (int t2 = 0; t2 < 2; t2++)
#pragma unroll
        for (int j = 0; j < 8; j++) {
            const int c = 16 * t2 + cq;
            const int f = 8 * j + f2;
            *(float2*)&g_A[(((size_t)b * 32 + c) * 1024 + h) * 64 + f] =
                make_float2(acc[t2][j][0], acc[t2][j][1]);
            *(float2*)&g_A[(((size_t)b * 32 + c + 8) * 1024 + h) * 64 + f] =
                make_float2(acc[t2][j][2], acc[t2][j][3]);
        }
}

// ---------------------------------------------------------------------------
// Stage B (fp32): partial X over a 64-h slice.  grid (16,32,2).
// ---------------------------------------------------------------------------
__global__ void __launch_bounds__(128) kB() {
    const int hq = blockIdx.x, c = blockIdx.y, b = blockIdx.z;
    __shared__ __align__(16) float2 As[32][33];
    __shared__ __align__(16) float4 EBs[32][64];
    const int t = threadIdx.x;
    const int k1l = t & 15;
    const int k2g = (t >> 4) * 4;
    ull acc[4][4] = {};
    const float* abase = g_A + ((size_t)(b * 32 + c) * 1024 + hq * 64) * 64;

    for (int ch = 0; ch < 2; ch++) {
        const int h0c = hq * 64 + ch * 32;
#pragma unroll
        for (int k = 0; k < 8; k++) {
            const int idx = t + k * 128;
            const int hh = idx >> 5, k2 = idx & 31;
            As[hh][k2] = *(const float2*)&abase[(ch * 32 + hh) * 64 + 2 * k2];
        }
#pragma unroll
        for (int k = 0; k < 16; k++) {
            const int idx = t + k * 128;
            const int hh = idx >> 6, k1 = idx & 63;
            EBs[hh][k1] = *(const float4*)&g_EB4[((h0c + hh) * 64 + k1) * 4];
        }
        __syncthreads();
#pragma unroll 4
        for (int hh = 0; hh < 32; hh++) {
            ull ar[4], ai[4];
#pragma unroll
            for (int j = 0; j < 4; j++) {
                const float2 a = As[hh][k2g + j];
                ar[j] = pack2(a.x, a.x);
                ai[j] = pack2(a.y, a.y);
            }
#pragma unroll
            for (int i = 0; i < 4; i++) {
                const ulonglong2 e = *(const ulonglong2*)&EBs[hh][k1l + 16 * i];
#pragma unroll
                for (int j = 0; j < 4; j++) { fma2(acc[i][j], ar[j], e.x); fma2(acc[i][j], ai[j], e.y); }
            }
        }
        __syncthreads();
    }
#pragma unroll
    for (int i = 0; i < 4; i++) {
        const int k1i = k1l + 16 * i;
#pragma unroll
        for (int j = 0; j < 4; j++)
            *(float2*)&g_Xp[(size_t)((((hq * 2 + b) * 32 + c) * 64 + k1i) * 32 + (k2g + j)) * 2]
                = unpack2(acc[i][j]);
    }
}

// Reduce 16 h-slice partials and apply combined weights.
__global__ void k_reduce_w() {
    const int id = blockIdx.x * 256 + threadIdx.x;   // 131072
    const int k2 = id & 31, k1i = (id >> 5) & 63, c = (id >> 11) & 31, b = id >> 16;
    float xr = 0.f, xi = 0.f;
#pragma unroll
    for (int hq = 0; hq < 16; hq++) {
        const float2 p = *(const float2*)
            &g_Xp[(size_t)((((hq * 2 + b) * 32 + c) * 64 + k1i) * 32 + k2) * 2];
        xr += p.x; xi += p.y;
    }
    const int wci = ((c << 6) + k1i) * 32 + k2;
    const float wr = g_Wc[wci * 2], wi = g_Wc[wci * 2 + 1];
    const float2 o = make_float2(xr * wr - xi * wi, xr * wi + xi * wr);
    *(float2*)&g_XW[((size_t)(b * 32 + c) * 64 + k1i) * 64 + 2 * k2] = o;
}

// ---------------------------------------------------------------------------
// Stage C (fp32): Z expansion.  grid (32,32,2), 32 h per CTA.
// ---------------------------------------------------------------------------
__global__ void __launch_bounds__(128) kC() {
    const int hc = blockIdx.x, c = blockIdx.y, b = blockIdx.z;
    const int h0 = hc * 32;
    __shared__ __align__(16) float2 XWs[64][33];
    __shared__ __align__(16) float4 ECs[32][17];
    const int t = threadIdx.x;
    const int hl = t & 15;
    const int k2g = (t >> 4) * 4;
    ull acc[2][4] = {};
#pragma unroll
    for (int k = 0; k < 16; k++) {
        const int idx = t + k * 128;
        const int k1 = idx >> 5, k2 = idx & 31;
        XWs[k1][k2] = *(const float2*)&g_XW[((size_t)(b * 32 + c) * 64 + k1) * 64 + 2 * k2];
    }
    for (int kc = 0; kc < 4; kc++) {
        __syncthreads();
#pragma unroll
        for (int k = 0; k < 4; k++) {
            const int idx = t + k * 128;
            const int hh = idx >> 4, kk = idx & 15;
            ECs[hh][kk] = *(const float4*)&g_EC4[((h0 + hh) * 64 + kc * 16 + kk) * 4];
        }
        __syncthreads();
#pragma unroll 4
        for (int kk = 0; kk < 16; kk++) {
            const int k1 = kc * 16 + kk;
            ull xr[4], xi[4];
#pragma unroll
            for (int j = 0; j < 4; j++) {
                const float2 xw = XWs[k1][k2g + j];
                xr[j] = pack2(xw.x, xw.x);
                xi[j] = pack2(xw.y, xw.y);
            }
#pragma unroll
            for (int i = 0; i < 2; i++) {
                const ulonglong2 e = *(const ulonglong2*)&ECs[hl + 16 * i][kk];
#pragma unroll
                for (int j = 0; j < 4; j++) { fma2(acc[i][j], xr[j], e.x); fma2(acc[i][j], xi[j], e.y); }
            }
        }
    }
#pragma unroll
    for (int i = 0; i < 2; i++) {
        const int h = h0 + hl + 16 * i;
#pragma unroll
        for (int j = 0; j < 4; j++)
            *(float2*)&g_Z[(((size_t)b * 1024 + h) * 32 + c) * 64 + 2 * (k2g + j)]
                = unpack2(acc[i][j]);
    }
}

// ---------------------------------------------------------------------------
// Stage D (HMMA): CTA per (wb=128w, hg=32h, b).  Per h:
//   y[m=w=128, n=c=32] = sum_f GD[w,f] * Z[c,f], K=64, split-bf16 x3.
// GD fragments hoisted out of the h loop.
// ---------------------------------------------------------------------------
__global__ void __launch_bounds__(128) kTD(float* __restrict__ y) {
    __shared__ __align__(16) char GH[18432];
    __shared__ __align__(16) char GL[18432];
    __shared__ __align__(16) char ZH[4608];
    __shared__ __align__(16) char ZL[4608];
    const uint32_t GHb = smem_u32(GH), GLb = smem_u32(GL);
    const uint32_t ZHb = smem_u32(ZH), ZLb = smem_u32(ZL);
    const int wb = blockIdx.x, hg = blockIdx.y, b = blockIdx.z;
    const int t = threadIdx.x, warp = t >> 5, lane = t & 31;

    const int g = lane >> 3, r = lane & 7;
    const int a_m = ((g & 1) << 3) + r;
    const int a_k = (g >> 1) << 3;
    const int b_n = ((g >> 1) << 3) + r;
    const int b_k = (g & 1) << 3;

    // GD tile: 128 w-rows x 64 f (hi+lo)
#pragma unroll
    for (int j = 0; j < 8; j++) {
        const int idx = t + j * 128;
        const int row = idx >> 3, q = idx & 7;
        const int off = row * 144 + q * 16;
        *(uint4*)(GH + off) = *(const uint4*)&g_GDh[(wb * 128 + row) * 64 + q * 8];
        *(uint4*)(GL + off) = *(const uint4*)&g_GDl[(wb * 128 + row) * 64 + q * 8];
    }
    __syncthreads();

    // hoisted GD fragments: [ks][t2][4]
    const int M0 = warp * 32;
    uint32_t gh[4][2][4], gl[4][2][4];
#pragma unroll
    for (int ks = 0; ks < 4; ks++)
#pragma unroll
        for (int t2 = 0; t2 < 2; t2++) {
            const uint32_t off =
                (uint32_t)((M0 + 16 * t2 + a_m) * 144 + (ks * 16 + a_k) * 2);
            ldmx4(gh[ks][t2], GHb + off);
            ldmx4(gl[ks][t2], GLb + off);
        }

    const int cq = lane >> 2, f2 = (lane & 3) * 2;
    for (int hh = 0; hh < 32; hh++) {
        const int h = hg * 32 + hh;
        const float* zp = &g_Z[(size_t)(b * 1024 + h) * 2048];
        __syncthreads();    // prev iteration's ldmatrix reads of Z done
        // Z: 32c x 64f -> split bf16 [n=c][k=f]
#pragma unroll
        for (int j = 0; j < 8; j++) {
            const int idx = t + j * 128;
            const int c = idx >> 5, fp = idx & 31;
            const float2 zv = *(const float2*)&zp[c * 64 + 2 * fp];
            const int off = c * 144 + fp * 4;
            uint32_t hv, lv;
            split2(zv.x, zv.y, hv, lv);
            *(uint32_t*)(ZH + off) = hv;
            *(uint32_t*)(ZL + off) = lv;
        }
        __syncthreads();
        float acc[2][4][4];
#pragma unroll
        for (int i = 0; i < 2; i++)
#pragma unroll
            for (int j = 0; j < 4; j++)
#pragma unroll
                for (int q = 0; q < 4; q++) acc[i][j][q] = 0.f;
#pragma unroll
        for (int ks = 0; ks < 4; ks++) {
#pragma unroll
            for (int jn = 0; jn < 2; jn++) {
                const uint32_t off =
                    (uint32_t)((jn * 16 + b_n) * 144 + (ks * 16 + b_k) * 2);
                uint32_t bh[4], bl[4];
                ldmx4(bh, ZHb + off);
                ldmx4(bl, ZLb + off);
#pragma unroll
                for (int t2 = 0; t2 < 2; t2++) {
                    mma_bf16(acc[t2][2 * jn],     gh[ks][t2], bh);
                    mma_bf16(acc[t2][2 * jn],     gh[ks][t2], bl);
                    mma_bf16(acc[t2][2 * jn],     gl[ks][t2], bh);
                    mma_bf16(acc[t2][2 * jn + 1], gh[ks][t2], bh + 2);
                    mma_bf16(acc[t2][2 * jn + 1], gh[ks][t2], bl + 2);
                    mma_bf16(acc[t2][2 * jn + 1], gl[ks][t2], bh + 2);
                }
            }
        }
        // write y[b,h,w,c]
        float* yb = y + (size_t)(b * 1024 + h) * 32768;
#pragma unroll
        for (int t2 = 0; t2 < 2; t2++)
#pragma unroll
            for (int j = 0; j < 4; j++) {
                const int w = wb * 128 + M0 + 16 * t2 + cq;
                const int c = 8 * j + f2;
                *(float2*)&yb[(size_t)w * 32 + c] =
                    make_float2(acc[t2][j][0], acc[t2][j][1]);
                *(float2*)&yb[(size_t)(w + 8) * 32 + c] =
                    make_float2(acc[t2][j][2], acc[t2][j][3]);
            }
    }
}

// ---------------------------------------------------------------------------
extern "C" void kernel_launch(void* const* d_in, const int* in_sizes, int n_in,
                              void* d_out, int out_size) {
    const float* x   = (const float*)d_in[0];
    const float* w0r = (const float*)d_in[1];
    const float* w0i = (const float*)d_in[2];
    const float* w1r = (const float*)d_in[3];
    const float* w1i = (const float*)d_in[4];
    const float* w2r = (const float*)d_in[5];
    const float* w2i = (const float*)d_in[6];
    float* y = (float*)d_out;

    cudaFuncSetAttribute(kTA, cudaFuncAttributeMaxDynamicSharedMemorySize, SMEM_KTA);

    k_init_tables<<<1024, 64>>>();
    k_init_w<<<256, 256>>>(w0r, w0i, w1r, w1i, w2r, w2i);
    kTA<<<dim3(256, 2), 128, SMEM_KTA>>>(x);
    kB<<<dim3(16, 32, 2), 128>>>();
    k_reduce_w<<<512, 256>>>();
    kC<<<dim3(32, 32, 2), 128>>>();
    kTD<<<dim3(8, 32, 2), 128>>>(y);
}

// round 13
// speedup vs baseline: 3.2204x; 1.0436x over previous
#include <cuda_runtime.h>
#include <cuda_bf16.h>
#include <cstdint>

// ---------------------------------------------------------------------------
// FNO spectral block: B=2, H=1024, W=1024, C=32, modes rows {0..31,992..1023},
// cols 0..31.  Stages A/D: warp-level bf16 mma.sync (split-bf16 3-MMA).
// Stages B/C: fp32 f32x2, 2 channels/CTA.  kC emits pre-split bf16 Z.
// ---------------------------------------------------------------------------

typedef unsigned long long ull;

// ---- device scratch (allocation-free) ----
__device__ float g_EB4[1024 * 64 * 4];               // [h][k1i]: (c,-s, s,c)
__device__ float g_EC4[1024 * 64 * 4];               // [h][k1i]: (c, s,-s,c)/H
__device__ float g_Wc [32 * 64 * 32 * 2];            // combined w0*(w1|w2)
__device__ __nv_bfloat16 g_FBh[64 * 1024];           // fwd DFT [fcol][w] hi
__device__ __nv_bfloat16 g_FBl[64 * 1024];           // fwd DFT lo
__device__ __nv_bfloat16 g_GDh[1024 * 64];           // inv DFT [w][fcol] hi
__device__ __nv_bfloat16 g_GDl[1024 * 64];           // inv DFT lo
__device__ float g_A  [(size_t)2 * 32 * 1024 * 64];  // [b][c][h][fcol]
__device__ float g_Xp [32 * 32 * 64 * 32 * 2];       // [hq*2+b][c][k1i][k2]
__device__ float g_XW [(size_t)2 * 32 * 64 * 64];    // [b][c][k1i][2k2]
__device__ __nv_bfloat16 g_Zh[(size_t)2 * 1024 * 32 * 64];  // Z split hi
__device__ __nv_bfloat16 g_Zl[(size_t)2 * 1024 * 32 * 64];  // Z split lo

// ---- packed fp32x2 helpers ----
__device__ __forceinline__ void fma2(ull& acc, ull a, ull b) {
    asm("fma.rn.f32x2 %0, %1, %2, %0;" : "+l"(acc) : "l"(a), "l"(b));
}
__device__ __forceinline__ ull pack2(float x, float y) {
    ull r; asm("mov.b64 %0, {%1, %2};" : "=l"(r) : "f"(x), "f"(y)); return r;
}
__device__ __forceinline__ float2 unpack2(ull v) {
    float2 r; asm("mov.b64 {%0, %1}, %2;" : "=f"(r.x), "=f"(r.y) : "l"(v)); return r;
}

// ---- mma.sync / ldmatrix helpers (no 'a'-suffix features) ----
__device__ __forceinline__ uint32_t smem_u32(const void* p) {
    uint32_t a;
    asm("{ .reg .u64 t; cvta.to.shared.u64 t, %1; cvt.u32.u64 %0, t; }" : "=r"(a) : "l"(p));
    return a;
}
__device__ __forceinline__ void mma_bf16(float* d, const uint32_t* a, const uint32_t* b) {
    asm("mma.sync.aligned.m16n8k16.row.col.f32.bf16.bf16.f32 "
        "{%0,%1,%2,%3}, {%4,%5,%6,%7}, {%8,%9}, {%0,%1,%2,%3};"
        : "+f"(d[0]), "+f"(d[1]), "+f"(d[2]), "+f"(d[3])
        : "r"(a[0]), "r"(a[1]), "r"(a[2]), "r"(a[3]), "r"(b[0]), "r"(b[1]));
}
__device__ __forceinline__ void ldmx4(uint32_t* r, uint32_t addr) {
    asm volatile("ldmatrix.sync.aligned.m8n8.x4.shared.b16 {%0,%1,%2,%3}, [%4];"
                 : "=r"(r[0]), "=r"(r[1]), "=r"(r[2]), "=r"(r[3]) : "r"(addr));
}
__device__ __forceinline__ void split2(float a, float b, uint32_t& hi, uint32_t& lo) {
    __nv_bfloat162 h = __float22bfloat162_rn(make_float2(a, b));
    const float2 hf = __bfloat1622float2(h);
    __nv_bfloat162 l = __float22bfloat162_rn(make_float2(a - hf.x, b - hf.y));
    hi = *(uint32_t*)&h;
    lo = *(uint32_t*)&l;
}

// ---------------------------------------------------------------------------
// Init: exact integer mod-1024 phase + float sincospif (FP64 pipe avoided).
// ---------------------------------------------------------------------------
__global__ void k_init_tables() {
    const int row = blockIdx.x;
    const int t = threadIdx.x;      // 0..63
    {
        const int k2 = t >> 1;
        const int r = (k2 * row) & 1023;
        float s, c;
        sincospif((float)r / 512.0f, &s, &c);
        const float vF = (t & 1) ? -s : c;
        const float sc = (k2 == 0 ? 1.0f : 2.0f) / 1024.0f;
        const float vG = (t & 1) ? (-sc * s) : (sc * c);
        const __nv_bfloat16 fh = __float2bfloat16(vF);
        g_FBh[t * 1024 + row] = fh;
        g_FBl[t * 1024 + row] = __float2bfloat16(vF - __bfloat162float(fh));
        const __nv_bfloat16 gh = __float2bfloat16(vG);
        g_GDh[row * 64 + t] = gh;
        g_GDl[row * 64 + t] = __float2bfloat16(vG - __bfloat162float(gh));
    }
    {
        const int k1i = t;
        const int k1 = (k1i < 32) ? k1i : (960 + k1i);
        const int r = (k1 * row) & 1023;
        float s, c;
        sincospif((float)r / 512.0f, &s, &c);
        float* eb = &g_EB4[(row * 64 + k1i) * 4];
        eb[0] = c;  eb[1] = -s;
        eb[2] = s;  eb[3] = c;
        const float inv = 1.0f / 1024.0f;
        float* ec = &g_EC4[(row * 64 + k1i) * 4];
        ec[0] = c * inv;   ec[1] = s * inv;
        ec[2] = -s * inv;  ec[3] = c * inv;
    }
}

__global__ void k_init_w(const float* __restrict__ w0r, const float* __restrict__ w0i,
                         const float* __restrict__ w1r, const float* __restrict__ w1i,
                         const float* __restrict__ w2r, const float* __restrict__ w2i) {
    const int idx = blockIdx.x * 256 + threadIdx.x;   // 65536
    const int k2 = idx & 31;
    const int k1i = (idx >> 5) & 63;
    const int c = idx >> 11;
    const float ar = w0r[c], ai = w0i[c];
    float br, bi;
    if (k1i < 32) { const int o = (c * 32 + k1i) * 32 + k2;        br = w1r[o]; bi = w1i[o]; }
    else          { const int o = (c * 32 + (k1i - 32)) * 32 + k2; br = w2r[o]; bi = w2i[o]; }
    g_Wc[idx * 2]     = ar * br - ai * bi;
    g_Wc[idx * 2 + 1] = ar * bi + ai * br;
}

// ---------------------------------------------------------------------------
// Stage A (HMMA, unchanged from R11): CTA per (4h, b).
// ---------------------------------------------------------------------------
#define XH_OFF 0
#define XL_OFF 18432
#define FH_OFF 36864
#define FL_OFF 46080
#define SMEM_KTA 55296

__global__ void __launch_bounds__(128) kTA(const float* __restrict__ x) {
    extern __shared__ __align__(16) char sm[];
    char* XH = sm + XH_OFF;  char* XL = sm + XL_OFF;
    char* FH = sm + FH_OFF;  char* FL = sm + FL_OFF;
    const uint32_t sb = smem_u32(sm);
    const int hg = blockIdx.x, b = blockIdx.y;
    const int t = threadIdx.x, warp = t >> 5, lane = t & 31;
    const int h0 = hg * 4;
    const float* xb = x + (size_t)(b * 1024 + h0) * 32768;

    const int g = lane >> 3, r = lane & 7;
    const int a_m = ((g & 1) << 3) + r;
    const int a_k = (g >> 1) << 3;
    const int b_n = ((g >> 1) << 3) + r;
    const int b_k = (g & 1) << 3;

    float acc[2][8][4];
#pragma unroll
    for (int i = 0; i < 2; i++)
#pragma unroll
        for (int j = 0; j < 8; j++)
#pragma unroll
            for (int q = 0; q < 4; q++) acc[i][j][q] = 0.f;

    const int M0 = warp * 32;
    for (int kc = 0; kc < 16; kc++) {
        const int w0 = kc * 64;
        __syncthreads();
#pragma unroll
        for (int j = 0; j < 8; j++) {
            const int idx = t + j * 128;
            const int c4 = idx & 7, wp = (idx >> 3) & 31, hh = idx >> 8;
            const float* p = xb + (size_t)hh * 32768 + (size_t)(w0 + 2 * wp) * 32 + c4 * 4;
            const float4 v0 = *(const float4*)p;
            const float4 v1 = *(const float4*)(p + 32);
            const float e0[4] = {v0.x, v0.y, v0.z, v0.w};
            const float e1[4] = {v1.x, v1.y, v1.z, v1.w};
#pragma unroll
            for (int i = 0; i < 4; i++) {
                const int m = hh * 32 + c4 * 4 + i;
                const int off = m * 144 + wp * 4;
                uint32_t hv, lv;
                split2(e0[i], e1[i], hv, lv);
                *(uint32_t*)(XH + off) = hv;
                *(uint32_t*)(XL + off) = lv;
            }
        }
#pragma unroll
        for (int j = 0; j < 4; j++) {
            const int idx = t + j * 128;
            const int f = idx >> 3, q = idx & 7;
            const int off = f * 144 + q * 16;
            *(uint4*)(FH + off) = *(const uint4*)&g_FBh[f * 1024 + w0 + q * 8];
            *(uint4*)(FL + off) = *(const uint4*)&g_FBl[f * 1024 + w0 + q * 8];
        }
        __syncthreads();
#pragma unroll
        for (int ks = 0; ks < 4; ks++) {
            const int K0 = ks * 16;
            uint32_t ah[2][4], al[2][4];
#pragma unroll
            for (int t2 = 0; t2 < 2; t2++) {
                const uint32_t ra =
                    sb + (uint32_t)((M0 + 16 * t2 + a_m) * 144 + (K0 + a_k) * 2);
                ldmx4(ah[t2], ra + XH_OFF);
                ldmx4(al[t2], ra + XL_OFF);
            }
#pragma unroll
            for (int jn = 0; jn < 4; jn++) {
                const uint32_t rb =
                    sb + (uint32_t)((jn * 16 + b_n) * 144 + (K0 + b_k) * 2);
                uint32_t bh[4], bl[4];
                ldmx4(bh, rb + FH_OFF);
                ldmx4(bl, rb + FL_OFF);
#pragma unroll
                for (int t2 = 0; t2 < 2; t2++) {
                    mma_bf16(acc[t2][2 * jn],     ah[t2], bh);
                    mma_bf16(acc[t2][2 * jn],     ah[t2], bl);
                    mma_bf16(acc[t2][2 * jn],     al[t2], bh);
                    mma_bf16(acc[t2][2 * jn + 1], ah[t2], bh + 2);
                    mma_bf16(acc[t2][2 * jn + 1], ah[t2], bl + 2);
                    mma_bf16(acc[t2][2 * jn + 1], al[t2], bh + 2);
                }
            }
        }
    }
    const int h = h0 + warp;
    const int cq = lane >> 2, f2 = (lane & 3) * 2;
#pragma unroll
    for (int t2 = 0; t2 < 2; t2++)
#pragma unroll
        for (int j = 0; j < 8; j++) {
            const int c = 16 * t2 + cq;
            const int f = 8 * j + f2;
            *(float2*)&g_A[(((size_t)b * 32 + c) * 1024 + h) * 64 + f] =
                make_float2(acc[t2][j][0], acc[t2][j][1]);
            *(float2*)&g_A[(((size_t)b * 32 + c + 8) * 1024 + h) * 64 + f] =
                make_float2(acc[t2][j][2], acc[t2][j][3]);
        }
}

// ---------------------------------------------------------------------------
// Stage B (fp32): 2 channels per CTA share the EB tile.  grid (16,16,2), 256t.
// ---------------------------------------------------------------------------
__global__ void __launch_bounds__(256) kB() {
    const int hq = blockIdx.x, cg = blockIdx.y, b = blockIdx.z;
    __shared__ __align__(16) float2 As[2][32][32];
    __shared__ __align__(16) float4 EBs[32][64];
    const int t = threadIdx.x, tb = t & 127, cl = t >> 7;
    const int k1l = tb & 15;
    const int k2g = (tb >> 4) * 4;
    ull acc[4][4] = {};

    for (int ch = 0; ch < 2; ch++) {
        const int h0c = hq * 64 + ch * 32;
        __syncthreads();
#pragma unroll
        for (int k = 0; k < 8; k++) {                 // 2048 float2 (both c)
            const int idx = t + k * 256;
            const int c2 = idx >> 10, hh = (idx >> 5) & 31, k2 = idx & 31;
            As[c2][hh][k2] = *(const float2*)
                &g_A[(((size_t)(b * 32 + cg * 2 + c2)) * 1024 + h0c + hh) * 64 + 2 * k2];
        }
#pragma unroll
        for (int k = 0; k < 8; k++) {                 // 2048 float4
            const int idx = t + k * 256;
            const int hh = idx >> 6, k1 = idx & 63;
            EBs[hh][k1] = *(const float4*)&g_EB4[((h0c + hh) * 64 + k1) * 4];
        }
        __syncthreads();
#pragma unroll 4
        for (int hh = 0; hh < 32; hh++) {
            ull ar[4], ai[4];
#pragma unroll
            for (int j = 0; j < 4; j++) {
                const float2 a = As[cl][hh][k2g + j];
                ar[j] = pack2(a.x, a.x);
                ai[j] = pack2(a.y, a.y);
            }
#pragma unroll
            for (int i = 0; i < 4; i++) {
                const ulonglong2 e = *(const ulonglong2*)&EBs[hh][k1l + 16 * i];
#pragma unroll
                for (int j = 0; j < 4; j++) { fma2(acc[i][j], ar[j], e.x); fma2(acc[i][j], ai[j], e.y); }
            }
        }
    }
    const int c = cg * 2 + cl;
#pragma unroll
    for (int i = 0; i < 4; i++) {
        const int k1i = k1l + 16 * i;
#pragma unroll
        for (int j = 0; j < 4; j++)
            *(float2*)&g_Xp[(size_t)((((hq * 2 + b) * 32 + c) * 64 + k1i) * 32 + (k2g + j)) * 2]
                = unpack2(acc[i][j]);
    }
}

// Reduce 16 h-slice partials and apply combined weights.
__global__ void k_reduce_w() {
    const int id = blockIdx.x * 256 + threadIdx.x;   // 131072
    const int k2 = id & 31, k1i = (id >> 5) & 63, c = (id >> 11) & 31, b = id >> 16;
    float xr = 0.f, xi = 0.f;
#pragma unroll
    for (int hq = 0; hq < 16; hq++) {
        const float2 p = *(const float2*)
            &g_Xp[(size_t)((((hq * 2 + b) * 32 + c) * 64 + k1i) * 32 + k2) * 2];
        xr += p.x; xi += p.y;
    }
    const int wci = ((c << 6) + k1i) * 32 + k2;
    const float wr = g_Wc[wci * 2], wi = g_Wc[wci * 2 + 1];
    const float2 o = make_float2(xr * wr - xi * wi, xr * wi + xi * wr);
    *(float2*)&g_XW[((size_t)(b * 32 + c) * 64 + k1i) * 64 + 2 * k2] = o;
}

// ---------------------------------------------------------------------------
// Stage C (fp32): 2 channels per CTA share the EC tile; emits split bf16 Z.
// grid (32,16,2), 256 thr, 32 h per CTA.
// ---------------------------------------------------------------------------
__global__ void __launch_bounds__(256) kC() {
    const int hc = blockIdx.x, cg = blockIdx.y, b = blockIdx.z;
    const int h0 = hc * 32;
    __shared__ __align__(16) float2 XWs[2][64][33];
    __shared__ __align__(16) float4 ECs[32][17];
    const int t = threadIdx.x, tb = t & 127, cl = t >> 7;
    const int hl = tb & 15;
    const int k2g = (tb >> 4) * 4;
    ull acc[2][4] = {};
#pragma unroll
    for (int k = 0; k < 16; k++) {                    // 4096 float2 (both c)
        const int idx = t + k * 256;
        const int c2 = idx >> 11, k1 = (idx >> 5) & 63, k2 = idx & 31;
        XWs[c2][k1][k2] = *(const float2*)
            &g_XW[((size_t)(b * 32 + cg * 2 + c2) * 64 + k1) * 64 + 2 * k2];
    }
    for (int kc = 0; kc < 4; kc++) {
        __syncthreads();
#pragma unroll
        for (int k = 0; k < 2; k++) {                 // 512 float4
            const int idx = t + k * 256;
            const int hh = idx >> 4, kk = idx & 15;
            ECs[hh][kk] = *(const float4*)&g_EC4[((h0 + hh) * 64 + kc * 16 + kk) * 4];
        }
        __syncthreads();
#pragma unroll 4
        for (int kk = 0; kk < 16; kk++) {
            const int k1 = kc * 16 + kk;
            ull xr[4], xi[4];
#pragma unroll
            for (int j = 0; j < 4; j++) {
                const float2 xw = XWs[cl][k1][k2g + j];
                xr[j] = pack2(xw.x, xw.x);
                xi[j] = pack2(xw.y, xw.y);
            }
#pragma unroll
            for (int i = 0; i < 2; i++) {
                const ulonglong2 e = *(const ulonglong2*)&ECs[hl + 16 * i][kk];
#pragma unroll
                for (int j = 0; j < 4; j++) { fma2(acc[i][j], xr[j], e.x); fma2(acc[i][j], xi[j], e.y); }
            }
        }
    }
    const int c = cg * 2 + cl;
#pragma unroll
    for (int i = 0; i < 2; i++) {
        const int h = h0 + hl + 16 * i;
#pragma unroll
        for (int j = 0; j < 4; j++) {
            const float2 v = unpack2(acc[i][j]);
            uint32_t hi, lo;
            split2(v.x, v.y, hi, lo);
            const size_t o = (((size_t)b * 1024 + h) * 32 + c) * 64 + 2 * (k2g + j);
            *(uint32_t*)&g_Zh[o] = hi;
            *(uint32_t*)&g_Zl[o] = lo;
        }
    }
}

// ---------------------------------------------------------------------------
// Stage D (HMMA): CTA per (wb=128w, hg=32h, b).  Z staged by pure bf16 copy.
// ---------------------------------------------------------------------------
__global__ void __launch_bounds__(128) kTD(float* __restrict__ y) {
    __shared__ __align__(16) char GH[18432];
    __shared__ __align__(16) char GL[18432];
    __shared__ __align__(16) char ZH[4608];
    __shared__ __align__(16) char ZL[4608];
    const uint32_t GHb = smem_u32(GH), GLb = smem_u32(GL);
    const uint32_t ZHb = smem_u32(ZH), ZLb = smem_u32(ZL);
    const int wb = blockIdx.x, hg = blockIdx.y, b = blockIdx.z;
    const int t = threadIdx.x, warp = t >> 5, lane = t & 31;

    const int g = lane >> 3, r = lane & 7;
    const int a_m = ((g & 1) << 3) + r;
    const int a_k = (g >> 1) << 3;
    const int b_n = ((g >> 1) << 3) + r;
    const int b_k = (g & 1) << 3;

#pragma unroll
    for (int j = 0; j < 8; j++) {
        const int idx = t + j * 128;
        const int row = idx >> 3, q = idx & 7;
        const int off = row * 144 + q * 16;
        *(uint4*)(GH + off) = *(const uint4*)&g_GDh[(wb * 128 + row) * 64 + q * 8];
        *(uint4*)(GL + off) = *(const uint4*)&g_GDl[(wb * 128 + row) * 64 + q * 8];
    }
    __syncthreads();

    const int M0 = warp * 32;
    uint32_t gh[4][2][4], gl[4][2][4];
#pragma unroll
    for (int ks = 0; ks < 4; ks++)
#pragma unroll
        for (int t2 = 0; t2 < 2; t2++) {
            const uint32_t off =
                (uint32_t)((M0 + 16 * t2 + a_m) * 144 + (ks * 16 + a_k) * 2);
            ldmx4(gh[ks][t2], GHb + off);
            ldmx4(gl[ks][t2], GLb + off);
        }

    const int cq = lane >> 2, f2 = (lane & 3) * 2;
    for (int hh = 0; hh < 32; hh++) {
        const int h = hg * 32 + hh;
        const size_t zb = (size_t)(b * 1024 + h) * 2048;
        __syncthreads();
#pragma unroll
        for (int j = 0; j < 2; j++) {                 // 256 uint4 per buffer
            const int idx = t + j * 128;
            const int row = idx >> 3, q = idx & 7;
            const int off = row * 144 + q * 16;
            *(uint4*)(ZH + off) = *(const uint4*)&g_Zh[zb + row * 64 + q * 8];
            *(uint4*)(ZL + off) = *(const uint4*)&g_Zl[zb + row * 64 + q * 8];
        }
        __syncthreads();
        float acc[2][4][4];
#pragma unroll
        for (int i = 0; i < 2; i++)
#pragma unroll
            for (int j = 0; j < 4; j++)
#pragma unroll
                for (int q = 0; q < 4; q++) acc[i][j][q] = 0.f;
#pragma unroll
        for (int ks = 0; ks < 4; ks++) {
#pragma unroll
            for (int jn = 0; jn < 2; jn++) {
                const uint32_t off =
                    (uint32_t)((jn * 16 + b_n) * 144 + (ks * 16 + b_k) * 2);
                uint32_t bh[4], bl[4];
                ldmx4(bh, ZHb + off);
                ldmx4(bl, ZLb + off);
#pragma unroll
                for (int t2 = 0; t2 < 2; t2++) {
                    mma_bf16(acc[t2][2 * jn],     gh[ks][t2], bh);
                    mma_bf16(acc[t2][2 * jn],     gh[ks][t2], bl);
                    mma_bf16(acc[t2][2 * jn],     gl[ks][t2], bh);
                    mma_bf16(acc[t2][2 * jn + 1], gh[ks][t2], bh + 2);
                    mma_bf16(acc[t2][2 * jn + 1], gh[ks][t2], bl + 2);
                    mma_bf16(acc[t2][2 * jn + 1], gl[ks][t2], bh + 2);
                }
            }
        }
        float* yb = y + (size_t)(b * 1024 + h) * 32768;
#pragma unroll
        for (int t2 = 0; t2 < 2; t2++)
#pragma unroll
            for (int j = 0; j < 4; j++) {
                const int w = wb * 128 + M0 + 16 * t2 + cq;
                const int c = 8 * j + f2;
                *(float2*)&yb[(size_t)w * 32 + c] =
                    make_float2(acc[t2][j][0], acc[t2][j][1]);
                *(float2*)&yb[(size_t)(w + 8) * 32 + c] =
                    make_float2(acc[t2][j][2], acc[t2][j][3]);
            }
    }
}

// ---------------------------------------------------------------------------
extern "C" void kernel_launch(void* const* d_in, const int* in_sizes, int n_in,
                              void* d_out, int out_size) {
    const float* x   = (const float*)d_in[0];
    const float* w0r = (const float*)d_in[1];
    const float* w0i = (const float*)d_in[2];
    const float* w1r = (const float*)d_in[3];
    const float* w1i = (const float*)d_in[4];
    const float* w2r = (const float*)d_in[5];
    const float* w2i = (const float*)d_in[6];
    float* y = (float*)d_out;

    cudaFuncSetAttribute(kTA, cudaFuncAttributeMaxDynamicSharedMemorySize, SMEM_KTA);

    k_init_tables<<<1024, 64>>>();
    k_init_w<<<256, 256>>>(w0r, w0i, w1r, w1i, w2r, w2i);
    kTA<<<dim3(256, 2), 128, SMEM_KTA>>>(x);
    kB<<<dim3(16, 16, 2), 256>>>();
    k_reduce_w<<<512, 256>>>();
    kC<<<dim3(32, 16, 2), 256>>>();
    kTD<<<dim3(8, 32, 2), 128>>>(y);
}

// round 14
// speedup vs baseline: 4.4791x; 1.3908x over previous
#include <cuda_runtime.h>
#include <cuda_fp16.h>
#include <cstdint>

// ---------------------------------------------------------------------------
// FNO spectral block: B=2, H=1024, W=1024, C=32, modes rows {0..31,992..1023},
// cols 0..31.
// Stages A/D: warp-level fp16 mma.sync, 2-MMA asymmetric split
//   (runtime operand single fp16, DFT matrix double fp16 hi+lo).
// Stages B/C: fp32 f32x2.  kC emits fp16 Z directly.
// ---------------------------------------------------------------------------

typedef unsigned long long ull;

// ---- device scratch (allocation-free) ----
__device__ float g_EB4[1024 * 64 * 4];               // [h][k1i]: (c,-s, s,c)
__device__ float g_EC4[1024 * 64 * 4];               // [h][k1i]: (c, s,-s,c)/H
__device__ float g_Wc [32 * 64 * 32 * 2];            // combined w0*(w1|w2)
__device__ __half g_FBh[64 * 1024];                  // fwd DFT [fcol][w] hi
__device__ __half g_FBl[64 * 1024];                  // fwd DFT lo
__device__ __half g_GDh[1024 * 64];                  // inv DFT [w][fcol] hi
__device__ __half g_GDl[1024 * 64];                  // inv DFT lo
__device__ float g_A  [(size_t)2 * 32 * 1024 * 64];  // [b][c][h][fcol]
__device__ float g_Xp [32 * 32 * 64 * 32 * 2];       // [hq*2+b][c][k1i][k2]
__device__ float g_XW [(size_t)2 * 32 * 64 * 64];    // [b][c][k1i][2k2]
__device__ __half g_Zh[(size_t)2 * 1024 * 32 * 64];  // Z fp16 [b][h][c][fcol]

// ---- packed fp32x2 helpers ----
__device__ __forceinline__ void fma2(ull& acc, ull a, ull b) {
    asm("fma.rn.f32x2 %0, %1, %2, %0;" : "+l"(acc) : "l"(a), "l"(b));
}
__device__ __forceinline__ ull pack2(float x, float y) {
    ull r; asm("mov.b64 %0, {%1, %2};" : "=l"(r) : "f"(x), "f"(y)); return r;
}
__device__ __forceinline__ float2 unpack2(ull v) {
    float2 r; asm("mov.b64 {%0, %1}, %2;" : "=f"(r.x), "=f"(r.y) : "l"(v)); return r;
}

// ---- mma.sync / ldmatrix helpers (no 'a'-suffix features) ----
__device__ __forceinline__ uint32_t smem_u32(const void* p) {
    uint32_t a;
    asm("{ .reg .u64 t; cvta.to.shared.u64 t, %1; cvt.u32.u64 %0, t; }" : "=r"(a) : "l"(p));
    return a;
}
__device__ __forceinline__ void mma_f16(float* d, const uint32_t* a, const uint32_t* b) {
    asm("mma.sync.aligned.m16n8k16.row.col.f32.f16.f16.f32 "
        "{%0,%1,%2,%3}, {%4,%5,%6,%7}, {%8,%9}, {%0,%1,%2,%3};"
        : "+f"(d[0]), "+f"(d[1]), "+f"(d[2]), "+f"(d[3])
        : "r"(a[0]), "r"(a[1]), "r"(a[2]), "r"(a[3]), "r"(b[0]), "r"(b[1]));
}
__device__ __forceinline__ void ldmx4(uint32_t* r, uint32_t addr) {
    asm volatile("ldmatrix.sync.aligned.m8n8.x4.shared.b16 {%0,%1,%2,%3}, [%4];"
                 : "=r"(r[0]), "=r"(r[1]), "=r"(r[2]), "=r"(r[3]) : "r"(addr));
}
__device__ __forceinline__ uint32_t f2h2(float a, float b) {
    __half2 h = __floats2half2_rn(a, b);
    return *(uint32_t*)&h;
}

// ---------------------------------------------------------------------------
// Init: exact integer mod-1024 phase + float sincospif.
// ---------------------------------------------------------------------------
__global__ void k_init_tables() {
    const int row = blockIdx.x;
    const int t = threadIdx.x;      // 0..63
    {
        const int k2 = t >> 1;
        const int r = (k2 * row) & 1023;
        float s, c;
        sincospif((float)r / 512.0f, &s, &c);
        const float vF = (t & 1) ? -s : c;
        const float sc = (k2 == 0 ? 1.0f : 2.0f) / 1024.0f;
        const float vG = (t & 1) ? (-sc * s) : (sc * c);
        const __half fh = __float2half_rn(vF);
        g_FBh[t * 1024 + row] = fh;
        g_FBl[t * 1024 + row] = __float2half_rn(vF - __half2float(fh));
        const __half gh = __float2half_rn(vG);
        g_GDh[row * 64 + t] = gh;
        g_GDl[row * 64 + t] = __float2half_rn(vG - __half2float(gh));
    }
    {
        const int k1i = t;
        const int k1 = (k1i < 32) ? k1i : (960 + k1i);
        const int r = (k1 * row) & 1023;
        float s, c;
        sincospif((float)r / 512.0f, &s, &c);
        float* eb = &g_EB4[(row * 64 + k1i) * 4];
        eb[0] = c;  eb[1] = -s;
        eb[2] = s;  eb[3] = c;
        const float inv = 1.0f / 1024.0f;
        float* ec = &g_EC4[(row * 64 + k1i) * 4];
        ec[0] = c * inv;   ec[1] = s * inv;
        ec[2] = -s * inv;  ec[3] = c * inv;
    }
}

__global__ void k_init_w(const float* __restrict__ w0r, const float* __restrict__ w0i,
                         const float* __restrict__ w1r, const float* __restrict__ w1i,
                         const float* __restrict__ w2r, const float* __restrict__ w2i) {
    const int idx = blockIdx.x * 256 + threadIdx.x;   // 65536
    const int k2 = idx & 31;
    const int k1i = (idx >> 5) & 63;
    const int c = idx >> 11;
    const float ar = w0r[c], ai = w0i[c];
    float br, bi;
    if (k1i < 32) { const int o = (c * 32 + k1i) * 32 + k2;        br = w1r[o]; bi = w1i[o]; }
    else          { const int o = (c * 32 + (k1i - 32)) * 32 + k2; br = w2r[o]; bi = w2i[o]; }
    g_Wc[idx * 2]     = ar * br - ai * bi;
    g_Wc[idx * 2 + 1] = ar * bi + ai * br;
}

// ---------------------------------------------------------------------------
// Stage A (HMMA fp16): CTA per (4h, b).  D[m=(hh,c)=128, n=fcol=64] =
//   sum_w x[h,w,c]*F[fcol,w].  K=1024 in 16 chunks of 64.
//   x single fp16; F = Fh + Fl (2 MMAs).  Rows padded to 144 B.
// ---------------------------------------------------------------------------
__global__ void __launch_bounds__(128) kTA(const float* __restrict__ x) {
    __shared__ __align__(16) char XH[18432];   // 128 m x 72 halfs
    __shared__ __align__(16) char FH[9216];    // 64 f x 72 halfs
    __shared__ __align__(16) char FL[9216];
    const uint32_t XHb = smem_u32(XH), FHb = smem_u32(FH), FLb = smem_u32(FL);
    const int hg = blockIdx.x, b = blockIdx.y;
    const int t = threadIdx.x, warp = t >> 5, lane = t & 31;
    const int h0 = hg * 4;
    const float* xb = x + (size_t)(b * 1024 + h0) * 32768;

    const int g = lane >> 3, r = lane & 7;
    const int a_m = ((g & 1) << 3) + r;
    const int a_k = (g >> 1) << 3;
    const int b_n = ((g >> 1) << 3) + r;
    const int b_k = (g & 1) << 3;

    float acc[2][8][4];
#pragma unroll
    for (int i = 0; i < 2; i++)
#pragma unroll
        for (int j = 0; j < 8; j++)
#pragma unroll
            for (int q = 0; q < 4; q++) acc[i][j][q] = 0.f;

    const int M0 = warp * 32;
    for (int kc = 0; kc < 16; kc++) {
        const int w0 = kc * 64;
        __syncthreads();
        // x: 4h x 64w x 32c -> fp16 [m=(hh,c)][k=w], 4 w per thread-iter
#pragma unroll
        for (int j = 0; j < 4; j++) {
            const int idx = t + j * 128;           // 512 = 4h*16wq*8c4
            const int c4 = idx & 7, wq = (idx >> 3) & 15, hh = idx >> 7;
            const float* p = xb + (size_t)hh * 32768 + (size_t)(w0 + 4 * wq) * 32 + c4 * 4;
            const float4 v0 = *(const float4*)p;
            const float4 v1 = *(const float4*)(p + 32);
            const float4 v2 = *(const float4*)(p + 64);
            const float4 v3 = *(const float4*)(p + 96);
            const float e0[4] = {v0.x, v0.y, v0.z, v0.w};
            const float e1[4] = {v1.x, v1.y, v1.z, v1.w};
            const float e2[4] = {v2.x, v2.y, v2.z, v2.w};
            const float e3[4] = {v3.x, v3.y, v3.z, v3.w};
#pragma unroll
            for (int i = 0; i < 4; i++) {
                const int m = hh * 32 + c4 * 4 + i;
                uint2 val;
                val.x = f2h2(e0[i], e1[i]);
                val.y = f2h2(e2[i], e3[i]);
                *(uint2*)(XH + m * 144 + wq * 8) = val;
            }
        }
        // F: 64 rows x 64 k halfs, hi + lo
#pragma unroll
        for (int j = 0; j < 4; j++) {
            const int idx = t + j * 128;           // 512 = 64f*8q
            const int f = idx >> 3, q = idx & 7;
            const int off = f * 144 + q * 16;
            *(uint4*)(FH + off) = *(const uint4*)&g_FBh[f * 1024 + w0 + q * 8];
            *(uint4*)(FL + off) = *(const uint4*)&g_FBl[f * 1024 + w0 + q * 8];
        }
        __syncthreads();
#pragma unroll
        for (int ks = 0; ks < 4; ks++) {
            const int K0 = ks * 16;
            uint32_t ah[2][4];
#pragma unroll
            for (int t2 = 0; t2 < 2; t2++)
                ldmx4(ah[t2], XHb + (uint32_t)((M0 + 16 * t2 + a_m) * 144 + (K0 + a_k) * 2));
#pragma unroll
            for (int jn = 0; jn < 4; jn++) {
                const uint32_t rb = (uint32_t)((jn * 16 + b_n) * 144 + (K0 + b_k) * 2);
                uint32_t bh[4], bl[4];
                ldmx4(bh, FHb + rb);
                ldmx4(bl, FLb + rb);
#pragma unroll
                for (int t2 = 0; t2 < 2; t2++) {
                    mma_f16(acc[t2][2 * jn],     ah[t2], bh);
                    mma_f16(acc[t2][2 * jn],     ah[t2], bl);
                    mma_f16(acc[t2][2 * jn + 1], ah[t2], bh + 2);
                    mma_f16(acc[t2][2 * jn + 1], ah[t2], bl + 2);
                }
            }
        }
    }
    const int h = h0 + warp;
    const int cq = lane >> 2, f2 = (lane & 3) * 2;
#pragma unroll
    for (int t2 = 0; t2 < 2; t2++)
#pragma unroll
        for (int j = 0; j < 8; j++) {
            const int c = 16 * t2 + cq;
            const int f = 8 * j + f2;
            *(float2*)&g_A[(((size_t)b * 32 + c) * 1024 + h) * 64 + f] =
                make_float2(acc[t2][j][0], acc[t2][j][1]);
            *(float2*)&g_A[(((size_t)b * 32 + c + 8) * 1024 + h) * 64 + f] =
                make_float2(acc[t2][j][2], acc[t2][j][3]);
        }
}

// ---------------------------------------------------------------------------
// Stage B (fp32): 2 channels per CTA share the EB tile.  grid (16,16,2), 256t.
// ---------------------------------------------------------------------------
__global__ void __launch_bounds__(256) kB() {
    const int hq = blockIdx.x, cg = blockIdx.y, b = blockIdx.z;
    __shared__ __align__(16) float2 As[2][32][32];
    __shared__ __align__(16) float4 EBs[32][64];
    const int t = threadIdx.x, tb = t & 127, cl = t >> 7;
    const int k1l = tb & 15;
    const int k2g = (tb >> 4) * 4;
    ull acc[4][4] = {};

    for (int ch = 0; ch < 2; ch++) {
        const int h0c = hq * 64 + ch * 32;
        __syncthreads();
#pragma unroll
        for (int k = 0; k < 8; k++) {
            const int idx = t + k * 256;
            const int c2 = idx >> 10, hh = (idx >> 5) & 31, k2 = idx & 31;
            As[c2][hh][k2] = *(const float2*)
                &g_A[(((size_t)(b * 32 + cg * 2 + c2)) * 1024 + h0c + hh) * 64 + 2 * k2];
        }
#pragma unroll
        for (int k = 0; k < 8; k++) {
            const int idx = t + k * 256;
            const int hh = idx >> 6, k1 = idx & 63;
            EBs[hh][k1] = *(const float4*)&g_EB4[((h0c + hh) * 64 + k1) * 4];
        }
        __syncthreads();
#pragma unroll 4
        for (int hh = 0; hh < 32; hh++) {
            ull ar[4], ai[4];
#pragma unroll
            for (int j = 0; j < 4; j++) {
                const float2 a = As[cl][hh][k2g + j];
                ar[j] = pack2(a.x, a.x);
                ai[j] = pack2(a.y, a.y);
            }
#pragma unroll
            for (int i = 0; i < 4; i++) {
                const ulonglong2 e = *(const ulonglong2*)&EBs[hh][k1l + 16 * i];
#pragma unroll
                for (int j = 0; j < 4; j++) { fma2(acc[i][j], ar[j], e.x); fma2(acc[i][j], ai[j], e.y); }
            }
        }
    }
    const int c = cg * 2 + cl;
#pragma unroll
    for (int i = 0; i < 4; i++) {
        const int k1i = k1l + 16 * i;
#pragma unroll
        for (int j = 0; j < 4; j++)
            *(float2*)&g_Xp[(size_t)((((hq * 2 + b) * 32 + c) * 64 + k1i) * 32 + (k2g + j)) * 2]
                = unpack2(acc[i][j]);
    }
}

// Reduce 16 h-slice partials and apply combined weights.
__global__ void k_reduce_w() {
    const int id = blockIdx.x * 256 + threadIdx.x;   // 131072
    const int k2 = id & 31, k1i = (id >> 5) & 63, c = (id >> 11) & 31, b = id >> 16;
    float xr = 0.f, xi = 0.f;
#pragma unroll
    for (int hq = 0; hq < 16; hq++) {
        const float2 p = *(const float2*)
            &g_Xp[(size_t)((((hq * 2 + b) * 32 + c) * 64 + k1i) * 32 + k2) * 2];
        xr += p.x; xi += p.y;
    }
    const int wci = ((c << 6) + k1i) * 32 + k2;
    const float wr = g_Wc[wci * 2], wi = g_Wc[wci * 2 + 1];
    const float2 o = make_float2(xr * wr - xi * wi, xr * wi + xi * wr);
    *(float2*)&g_XW[((size_t)(b * 32 + c) * 64 + k1i) * 64 + 2 * k2] = o;
}

// ---------------------------------------------------------------------------
// Stage C (fp32): 2 channels per CTA; emits fp16 Z.  grid (32,16,2), 256t.
// ---------------------------------------------------------------------------
__global__ void __launch_bounds__(256) kC() {
    const int hc = blockIdx.x, cg = blockIdx.y, b = blockIdx.z;
    const int h0 = hc * 32;
    __shared__ __align__(16) float2 XWs[2][64][33];
    __shared__ __align__(16) float4 ECs[32][17];
    const int t = threadIdx.x, tb = t & 127, cl = t >> 7;
    const int hl = tb & 15;
    const int k2g = (tb >> 4) * 4;
    ull acc[2][4] = {};
#pragma unroll
    for (int k = 0; k < 16; k++) {
        const int idx = t + k * 256;
        const int c2 = idx >> 11, k1 = (idx >> 5) & 63, k2 = idx & 31;
        XWs[c2][k1][k2] = *(const float2*)
            &g_XW[((size_t)(b * 32 + cg * 2 + c2) * 64 + k1) * 64 + 2 * k2];
    }
    for (int kc = 0; kc < 4; kc++) {
        __syncthreads();
#pragma unroll
        for (int k = 0; k < 2; k++) {
            const int idx = t + k * 256;
            const int hh = idx >> 4, kk = idx & 15;
            ECs[hh][kk] = *(const float4*)&g_EC4[((h0 + hh) * 64 + kc * 16 + kk) * 4];
        }
        __syncthreads();
#pragma unroll 4
        for (int kk = 0; kk < 16; kk++) {
            const int k1 = kc * 16 + kk;
            ull xr[4], xi[4];
#pragma unroll
            for (int j = 0; j < 4; j++) {
                const float2 xw = XWs[cl][k1][k2g + j];
                xr[j] = pack2(xw.x, xw.x);
                xi[j] = pack2(xw.y, xw.y);
            }
#pragma unroll
            for (int i = 0; i < 2; i++) {
                const ulonglong2 e = *(const ulonglong2*)&ECs[hl + 16 * i][kk];
#pragma unroll
                for (int j = 0; j < 4; j++) { fma2(acc[i][j], xr[j], e.x); fma2(acc[i][j], xi[j], e.y); }
            }
        }
    }
    const int c = cg * 2 + cl;
#pragma unroll
    for (int i = 0; i < 2; i++) {
        const int h = h0 + hl + 16 * i;
#pragma unroll
        for (int j = 0; j < 4; j++) {
            const float2 v = unpack2(acc[i][j]);
            const size_t o = (((size_t)b * 1024 + h) * 32 + c) * 64 + 2 * (k2g + j);
            *(uint32_t*)&g_Zh[o] = f2h2(v.x, v.y);
        }
    }
}

// ---------------------------------------------------------------------------
// Stage D (HMMA fp16): CTA per (wb=128w, hg=32h, b).  Per h:
//   y[m=w=128, n=c=32] = sum_f GD[w,f]*Z[c,f], K=64.
//   GD = GDh + GDl (2 MMAs), Z single fp16.  GD fragments hoisted.
// ---------------------------------------------------------------------------
__global__ void __launch_bounds__(128) kTD(float* __restrict__ y) {
    __shared__ __align__(16) char GH[18432];
    __shared__ __align__(16) char GL[18432];
    __shared__ __align__(16) char ZH[4608];
    const uint32_t GHb = smem_u32(GH), GLb = smem_u32(GL), ZHb = smem_u32(ZH);
    const int wb = blockIdx.x, hg = blockIdx.y, b = blockIdx.z;
    const int t = threadIdx.x, warp = t >> 5, lane = t & 31;

    const int g = lane >> 3, r = lane & 7;
    const int a_m = ((g & 1) << 3) + r;
    const int a_k = (g >> 1) << 3;
    const int b_n = ((g >> 1) << 3) + r;
    const int b_k = (g & 1) << 3;

#pragma unroll
    for (int j = 0; j < 8; j++) {
        const int idx = t + j * 128;
        const int row = idx >> 3, q = idx & 7;
        const int off = row * 144 + q * 16;
        *(uint4*)(GH + off) = *(const uint4*)&g_GDh[(wb * 128 + row) * 64 + q * 8];
        *(uint4*)(GL + off) = *(const uint4*)&g_GDl[(wb * 128 + row) * 64 + q * 8];
    }
    __syncthreads();

    const int M0 = warp * 32;
    uint32_t gh[4][2][4], gl[4][2][4];
#pragma unroll
    for (int ks = 0; ks < 4; ks++)
#pragma unroll
        for (int t2 = 0; t2 < 2; t2++) {
            const uint32_t off =
                (uint32_t)((M0 + 16 * t2 + a_m) * 144 + (ks * 16 + a_k) * 2);
            ldmx4(gh[ks][t2], GHb + off);
            ldmx4(gl[ks][t2], GLb + off);
        }

    const int cq = lane >> 2, f2 = (lane & 3) * 2;
    for (int hh = 0; hh < 32; hh++) {
        const int h = hg * 32 + hh;
        const size_t zb = (size_t)(b * 1024 + h) * 2048;
        __syncthreads();
#pragma unroll
        for (int j = 0; j < 2; j++) {                 // 256 uint4
            const int idx = t + j * 128;
            const int row = idx >> 3, q = idx & 7;
            *(uint4*)(ZH + row * 144 + q * 16) = *(const uint4*)&g_Zh[zb + row * 64 + q * 8];
        }
        __syncthreads();
        float acc[2][4][4];
#pragma unroll
        for (int i = 0; i < 2; i++)
#pragma unroll
            for (int j = 0; j < 4; j++)
#pragma unroll
                for (int q = 0; q < 4; q++) acc[i][j][q] = 0.f;
#pragma unroll
        for (int ks = 0; ks < 4; ks++) {
#pragma unroll
            for (int jn = 0; jn < 2; jn++) {
                const uint32_t off =
                    (uint32_t)((jn * 16 + b_n) * 144 + (ks * 16 + b_k) * 2);
                uint32_t bh[4];
                ldmx4(bh, ZHb + off);
#pragma unroll
                for (int t2 = 0; t2 < 2; t2++) {
                    mma_f16(acc[t2][2 * jn],     gh[ks][t2], bh);
                    mma_f16(acc[t2][2 * jn],     gl[ks][t2], bh);
                    mma_f16(acc[t2][2 * jn + 1], gh[ks][t2], bh + 2);
                    mma_f16(acc[t2][2 * jn + 1], gl[ks][t2], bh + 2);
                }
            }
        }
        float* yb = y + (size_t)(b * 1024 + h) * 32768;
#pragma unroll
        for (int t2 = 0; t2 < 2; t2++)
#pragma unroll
            for (int j = 0; j < 4; j++) {
                const int w = wb * 128 + M0 + 16 * t2 + cq;
                const int c = 8 * j + f2;
                *(float2*)&yb[(size_t)w * 32 + c] =
                    make_float2(acc[t2][j][0], acc[t2][j][1]);
                *(float2*)&yb[(size_t)(w + 8) * 32 + c] =
                    make_float2(acc[t2][j][2], acc[t2][j][3]);
            }
    }
}

// ---------------------------------------------------------------------------
extern "C" void kernel_launch(void* const* d_in, const int* in_sizes, int n_in,
                              void* d_out, int out_size) {
    const float* x   = (const float*)d_in[0];
    const float* w0r = (const float*)d_in[1];
    const float* w0i = (const float*)d_in[2];
    const float* w1r = (const float*)d_in[3];
    const float* w1i = (const float*)d_in[4];
    const float* w2r = (const float*)d_in[5];
    const float* w2i = (const float*)d_in[6];
    float* y = (float*)d_out;

    k_init_tables<<<1024, 64>>>();
    k_init_w<<<256, 256>>>(w0r, w0i, w1r, w1i, w2r, w2i);
    kTA<<<dim3(256, 2), 128>>>(x);
    kB<<<dim3(16, 16, 2), 256>>>();
    k_reduce_w<<<512, 256>>>();
    kC<<<dim3(32, 16, 2), 256>>>();
    kTD<<<dim3(8, 32, 2), 128>>>(y);
}